// round 1
// baseline (speedup 1.0000x reference)
#include <cuda_runtime.h>
#include <math.h>

// Problem constants: B=4, H=W=64 -> N=4096 tokens, C=256, GROUPS=8
#define B_ 4
#define NTOK 4096        // H*W
#define C_ 256
#define GRP 8
#define CG 32            // C/GROUPS
#define ROWS_TOT (B_*NTOK)   // 16384

// ---------------- scratch (device globals; no allocations allowed) -------------
__device__ float g_mean[B_*GRP];
__device__ float g_rstd[B_*GRP];
__device__ float g_xn[ROWS_TOT*C_];     // normalized input (also residual)
__device__ float g_q[ROWS_TOT*C_];
__device__ float g_k[ROWS_TOT*C_];
__device__ float g_v[ROWS_TOT*C_];
__device__ float g_o[ROWS_TOT*C_];      // attn @ V
__device__ float g_attn[(size_t)B_*NTOK*NTOK]; // 256 MB logits / probs

// ---------------- GroupNorm stats: one block per (b,g) -------------------------
__global__ __launch_bounds__(1024) void gn_stats(const float* __restrict__ x) {
    int bg = blockIdx.x;            // 0..31
    int b = bg >> 3, g = bg & 7;
    const float* xb = x + (size_t)b * NTOK * C_ + g * CG;
    float s = 0.f, ss = 0.f;
    for (int i = threadIdx.x; i < NTOK * CG; i += blockDim.x) {
        int n = i >> 5, c = i & 31;
        float v = __ldg(&xb[(size_t)n * C_ + c]);
        s += v; ss += v * v;
    }
    __shared__ float sh1[1024], sh2[1024];
    int t = threadIdx.x;
    sh1[t] = s; sh2[t] = ss;
    __syncthreads();
    for (int o = 512; o > 0; o >>= 1) {
        if (t < o) { sh1[t] += sh1[t + o]; sh2[t] += sh2[t + o]; }
        __syncthreads();
    }
    if (t == 0) {
        float inv = 1.f / (float)(NTOK * CG);
        float m = sh1[0] * inv;
        float var = sh2[0] * inv - m * m;
        g_mean[bg] = m;
        g_rstd[bg] = rsqrtf(var + 1e-3f);
    }
}

// ---------------- GroupNorm apply (elementwise, float4) -------------------------
__global__ __launch_bounds__(256) void gn_norm(const float* __restrict__ x,
                                               const float* __restrict__ gamma,
                                               const float* __restrict__ beta) {
    size_t i4 = (size_t)blockIdx.x * blockDim.x + threadIdx.x; // float4 index
    size_t i = i4 * 4;
    int c = (int)(i & (C_ - 1));
    size_t row = i >> 8;            // 0..16383
    int b = (int)(row >> 12);       // row / 4096
    int bg = b * GRP + (c >> 5);
    float m = g_mean[bg], r = g_rstd[bg];
    float4 xv = ((const float4*)x)[i4];
    float4 gv = *(const float4*)(gamma + c);
    float4 bv = *(const float4*)(beta + c);
    float4 o;
    o.x = (xv.x - m) * r * gv.x + bv.x;
    o.y = (xv.y - m) * r * gv.y + bv.y;
    o.z = (xv.z - m) * r * gv.z + bv.z;
    o.w = (xv.w - m) * r * gv.w + bv.w;
    ((float4*)g_xn)[i4] = o;
}

// ---------------- 128x128x8 fp32 SGEMM, 8x8 microtile ---------------------------
// TB: B stored [N,K] (compute A @ B^T). BIAS: +bias[col]. RES: +res[row*N+col].
// C = (A@B(^T)) * scale (+bias) (+res)
template<bool TB, bool BIAS, bool RES>
__global__ __launch_bounds__(256) void gemm128(
    const float* __restrict__ A, const float* __restrict__ B,
    const float* __restrict__ bias, const float* __restrict__ res,
    float* __restrict__ C, int M, int N, int K,
    long sA, long sB, long sC, float scale)
{
    __shared__ float As[8][128];
    __shared__ float Bs[8][128];
    const int tid = threadIdx.x;
    const int tx = tid & 15, ty = tid >> 4;
    const int row0 = blockIdx.y * 128;
    const int col0 = blockIdx.x * 128;
    const float* Ab = A + (size_t)blockIdx.z * sA;
    const float* Bb = B + (size_t)blockIdx.z * sB;
    float* Cb = C + (size_t)blockIdx.z * sC;

    float acc[8][8];
#pragma unroll
    for (int i = 0; i < 8; i++)
#pragma unroll
        for (int j = 0; j < 8; j++) acc[i][j] = 0.f;

    const int arow = tid >> 1;            // 0..127
    const int ak4  = (tid & 1) * 4;       // 0 or 4
    const int bkr  = tid >> 5;            // 0..7   (NN path)
    const int bc4  = (tid & 31) * 4;      // 0..124 (NN path)

    for (int k0 = 0; k0 < K; k0 += 8) {
        float4 av = *(const float4*)(Ab + (size_t)(row0 + arow) * K + k0 + ak4);
        float4 bv;
        if (TB) bv = *(const float4*)(Bb + (size_t)(col0 + arow) * K + k0 + ak4);
        else    bv = *(const float4*)(Bb + (size_t)(k0 + bkr) * N + col0 + bc4);

        __syncthreads();
        As[ak4 + 0][arow] = av.x;
        As[ak4 + 1][arow] = av.y;
        As[ak4 + 2][arow] = av.z;
        As[ak4 + 3][arow] = av.w;
        if (TB) {
            Bs[ak4 + 0][arow] = bv.x;
            Bs[ak4 + 1][arow] = bv.y;
            Bs[ak4 + 2][arow] = bv.z;
            Bs[ak4 + 3][arow] = bv.w;
        } else {
            *(float4*)&Bs[bkr][bc4] = bv;
        }
        __syncthreads();

#pragma unroll
        for (int k = 0; k < 8; k++) {
            float4 a0 = *(const float4*)&As[k][ty * 4];
            float4 a1 = *(const float4*)&As[k][64 + ty * 4];
            float4 b0 = *(const float4*)&Bs[k][tx * 4];
            float4 b1 = *(const float4*)&Bs[k][64 + tx * 4];
            float ar[8] = {a0.x, a0.y, a0.z, a0.w, a1.x, a1.y, a1.z, a1.w};
            float br[8] = {b0.x, b0.y, b0.z, b0.w, b1.x, b1.y, b1.z, b1.w};
#pragma unroll
            for (int i = 0; i < 8; i++)
#pragma unroll
                for (int j = 0; j < 8; j++)
                    acc[i][j] = fmaf(ar[i], br[j], acc[i][j]);
        }
    }

    // epilogue: vectorized float4 stores (cols tx*4.. and 64+tx*4.. contiguous)
#pragma unroll
    for (int ih = 0; ih < 2; ih++) {
#pragma unroll
        for (int i = 0; i < 4; i++) {
            int r = row0 + ih * 64 + ty * 4 + i;
#pragma unroll
            for (int jh = 0; jh < 2; jh++) {
                int c = col0 + jh * 64 + tx * 4;
                float4 v;
                v.x = acc[ih * 4 + i][jh * 4 + 0] * scale;
                v.y = acc[ih * 4 + i][jh * 4 + 1] * scale;
                v.z = acc[ih * 4 + i][jh * 4 + 2] * scale;
                v.w = acc[ih * 4 + i][jh * 4 + 3] * scale;
                if (BIAS) {
                    float4 bb = *(const float4*)(bias + c);
                    v.x += bb.x; v.y += bb.y; v.z += bb.z; v.w += bb.w;
                }
                if (RES) {
                    float4 rr = *(const float4*)(res + (size_t)r * N + c);
                    v.x += rr.x; v.y += rr.y; v.z += rr.z; v.w += rr.w;
                }
                *(float4*)(Cb + (size_t)r * N + c) = v;
            }
        }
    }
}

// ---------------- row softmax over 4096, register-resident ---------------------
__global__ __launch_bounds__(256) void softmax4096(float* __restrict__ S) {
    float* row = S + (size_t)blockIdx.x * 4096;
    int t = threadIdx.x;
    float4 v[4];
#pragma unroll
    for (int i = 0; i < 4; i++) v[i] = ((const float4*)row)[t + 256 * i];

    float m = -1e30f;
#pragma unroll
    for (int i = 0; i < 4; i++) {
        m = fmaxf(m, fmaxf(fmaxf(v[i].x, v[i].y), fmaxf(v[i].z, v[i].w)));
    }
#pragma unroll
    for (int o = 16; o > 0; o >>= 1) m = fmaxf(m, __shfl_xor_sync(0xffffffffu, m, o));
    __shared__ float sm[8];
    if ((t & 31) == 0) sm[t >> 5] = m;
    __syncthreads();
    float bm = sm[0];
#pragma unroll
    for (int i = 1; i < 8; i++) bm = fmaxf(bm, sm[i]);

    float sum = 0.f;
#pragma unroll
    for (int i = 0; i < 4; i++) {
        v[i].x = __expf(v[i].x - bm); sum += v[i].x;
        v[i].y = __expf(v[i].y - bm); sum += v[i].y;
        v[i].z = __expf(v[i].z - bm); sum += v[i].z;
        v[i].w = __expf(v[i].w - bm); sum += v[i].w;
    }
#pragma unroll
    for (int o = 16; o > 0; o >>= 1) sum += __shfl_xor_sync(0xffffffffu, sum, o);
    __shared__ float ss[8];
    if ((t & 31) == 0) ss[t >> 5] = sum;
    __syncthreads();
    float tot = 0.f;
#pragma unroll
    for (int i = 0; i < 8; i++) tot += ss[i];
    float inv = 1.f / tot;
#pragma unroll
    for (int i = 0; i < 4; i++) {
        v[i].x *= inv; v[i].y *= inv; v[i].z *= inv; v[i].w *= inv;
        ((float4*)row)[t + 256 * i] = v[i];
    }
}

// -------------------------------- launch ---------------------------------------
extern "C" void kernel_launch(void* const* d_in, const int* in_sizes, int n_in,
                              void* d_out, int out_size) {
    const float* x     = (const float*)d_in[0];
    const float* gamma = (const float*)d_in[1];
    const float* beta  = (const float*)d_in[2];
    const float* Wq    = (const float*)d_in[3];
    const float* bq    = (const float*)d_in[4];
    const float* Wk    = (const float*)d_in[5];
    const float* bk    = (const float*)d_in[6];
    const float* Wv    = (const float*)d_in[7];
    const float* bv    = (const float*)d_in[8];
    const float* Wp    = (const float*)d_in[9];
    const float* bp    = (const float*)d_in[10];
    float* out = (float*)d_out;
    (void)in_sizes; (void)n_in; (void)out_size;

    float *xn, *q, *k, *v, *o, *attn;
    cudaGetSymbolAddress((void**)&xn,   g_xn);
    cudaGetSymbolAddress((void**)&q,    g_q);
    cudaGetSymbolAddress((void**)&k,    g_k);
    cudaGetSymbolAddress((void**)&v,    g_v);
    cudaGetSymbolAddress((void**)&o,    g_o);
    cudaGetSymbolAddress((void**)&attn, g_attn);

    // GroupNorm
    gn_stats<<<B_ * GRP, 1024>>>(x);
    gn_norm<<<(ROWS_TOT * C_ / 4) / 256, 256>>>(x, gamma, beta);

    // QKV projections: [16384,256] @ [256,256] + bias
    dim3 gQKV(C_ / 128, ROWS_TOT / 128, 1);
    gemm128<false, true, false><<<gQKV, 256>>>(xn, Wq, bq, nullptr, q,
                                               ROWS_TOT, C_, C_, 0, 0, 0, 1.f);
    gemm128<false, true, false><<<gQKV, 256>>>(xn, Wk, bk, nullptr, k,
                                               ROWS_TOT, C_, C_, 0, 0, 0, 1.f);
    gemm128<false, true, false><<<gQKV, 256>>>(xn, Wv, bv, nullptr, v,
                                               ROWS_TOT, C_, C_, 0, 0, 0, 1.f);

    // logits S = (Q @ K^T) * C^-0.5, batched over B
    dim3 gQK(NTOK / 128, NTOK / 128, B_);
    gemm128<true, false, false><<<gQK, 256>>>(q, k, nullptr, nullptr, attn,
                                              NTOK, NTOK, C_,
                                              (long)NTOK * C_, (long)NTOK * C_,
                                              (long)NTOK * NTOK, 0.0625f);

    // softmax over rows
    softmax4096<<<B_ * NTOK, 256>>>(attn);

    // O = P @ V, batched
    dim3 gAV(C_ / 128, NTOK / 128, B_);
    gemm128<false, false, false><<<gAV, 256>>>(attn, v, nullptr, nullptr, o,
                                               NTOK, C_, NTOK,
                                               (long)NTOK * NTOK, (long)NTOK * C_,
                                               (long)NTOK * C_, 1.f);

    // final projection + bias + residual (normalized input), direct to d_out
    gemm128<false, true, true><<<gQKV, 256>>>(o, Wp, bp, xn, out,
                                              ROWS_TOT, C_, C_, 0, 0, 0, 1.f);
}

// round 4
// speedup vs baseline: 2.7633x; 2.7633x over previous
#include <cuda_runtime.h>
#include <cstdint>
#include <math.h>

// Problem constants: B=4, H=W=64 -> N=4096 tokens, C=256, GROUPS=8
#define B_ 4
#define NTOK 4096
#define C_ 256
#define GRP 8
#define CG 32
#define ROWS_TOT (B_*NTOK)   // 16384

// ---------------- scratch (device globals) ------------------------------------
__device__ float g_mean[B_*GRP];
__device__ float g_rstd[B_*GRP];
__device__ float g_xn[ROWS_TOT*C_];     // normalized input (tf32-rounded), residual
__device__ float g_q[ROWS_TOT*C_];
__device__ float g_k[ROWS_TOT*C_];
__device__ float g_vT[ROWS_TOT*C_];     // V transposed: [C_][ROWS_TOT]
__device__ float g_o[ROWS_TOT*C_];
__device__ float g_wt[4*C_*C_];         // transposed weights (tf32-rounded)
__device__ float g_attn[(size_t)B_*NTOK*NTOK];

// ---------------- helpers -------------------------------------------------------
__device__ __forceinline__ uint32_t smem_u32(const void* p) {
    uint32_t a;
    asm("{ .reg .u64 t; cvta.to.shared.u64 t, %1; cvt.u32.u64 %0, t; }" : "=r"(a) : "l"(p));
    return a;
}
__device__ __forceinline__ float rna_tf32(float x) {
    uint32_t r; asm("cvt.rna.tf32.f32 %0, %1;" : "=r"(r) : "f"(x));
    return __uint_as_float(r);
}
__device__ __forceinline__ void cp16(uint32_t dst, const void* src) {
    asm volatile("cp.async.cg.shared.global [%0], [%1], 16;" :: "r"(dst), "l"(src));
}
__device__ __forceinline__ float lds32(uint32_t a) {
    float v; asm volatile("ld.shared.f32 %0, [%1];" : "=f"(v) : "r"(a));
    return v;
}
#define SWZ128(o) ((o) ^ (((o) >> 3) & 0x70))

// m16n8k8 tf32 MMA, fp32 accumulate (portable HMMA path; tcgen05 is rejected
// by this harness's compute_103 PTX target).
__device__ __forceinline__ void mma1688(float* d, const float* a, const float* b) {
    asm volatile(
        "mma.sync.aligned.m16n8k8.row.col.f32.tf32.tf32.f32 "
        "{%0,%1,%2,%3}, {%4,%5,%6,%7}, {%8,%9}, {%0,%1,%2,%3};"
        : "+f"(d[0]), "+f"(d[1]), "+f"(d[2]), "+f"(d[3])
        : "r"(__float_as_uint(a[0])), "r"(__float_as_uint(a[1])),
          "r"(__float_as_uint(a[2])), "r"(__float_as_uint(a[3])),
          "r"(__float_as_uint(b[0])), "r"(__float_as_uint(b[1])));
}

// ---------------- GroupNorm stats ----------------------------------------------
__global__ __launch_bounds__(1024) void gn_stats(const float* __restrict__ x) {
    int bg = blockIdx.x;
    int b = bg >> 3, g = bg & 7;
    const float* xb = x + (size_t)b * NTOK * C_ + g * CG;
    float s = 0.f, ss = 0.f;
    for (int i = threadIdx.x; i < NTOK * CG; i += blockDim.x) {
        int n = i >> 5, c = i & 31;
        float v = __ldg(&xb[(size_t)n * C_ + c]);
        s += v; ss += v * v;
    }
    __shared__ float sh1[1024], sh2[1024];
    int t = threadIdx.x;
    sh1[t] = s; sh2[t] = ss;
    __syncthreads();
    for (int o = 512; o > 0; o >>= 1) {
        if (t < o) { sh1[t] += sh1[t + o]; sh2[t] += sh2[t + o]; }
        __syncthreads();
    }
    if (t == 0) {
        float inv = 1.f / (float)(NTOK * CG);
        float m = sh1[0] * inv;
        float var = sh2[0] * inv - m * m;
        g_mean[bg] = m;
        g_rstd[bg] = rsqrtf(var + 1e-3f);
    }
}

// ---------------- GroupNorm apply (tf32-rounded output) -------------------------
__global__ __launch_bounds__(256) void gn_norm(const float* __restrict__ x,
                                               const float* __restrict__ gamma,
                                               const float* __restrict__ beta) {
    size_t i4 = (size_t)blockIdx.x * blockDim.x + threadIdx.x;
    size_t i = i4 * 4;
    int c = (int)(i & (C_ - 1));
    size_t row = i >> 8;
    int b = (int)(row >> 12);
    int bg = b * GRP + (c >> 5);
    float m = g_mean[bg], r = g_rstd[bg];
    float4 xv = ((const float4*)x)[i4];
    float4 gv = *(const float4*)(gamma + c);
    float4 bv = *(const float4*)(beta + c);
    float4 o;
    o.x = rna_tf32((xv.x - m) * r * gv.x + bv.x);
    o.y = rna_tf32((xv.y - m) * r * gv.y + bv.y);
    o.z = rna_tf32((xv.z - m) * r * gv.z + bv.z);
    o.w = rna_tf32((xv.w - m) * r * gv.w + bv.w);
    ((float4*)g_xn)[i4] = o;
}

// ---------------- weight transpose (rounded to tf32) ----------------------------
__global__ __launch_bounds__(256) void transposeW(const float* __restrict__ W,
                                                  float* __restrict__ Wt) {
    __shared__ float t[32][33];
    int c0 = blockIdx.x * 32, k0 = blockIdx.y * 32;
    int tx = threadIdx.x, ty = threadIdx.y;
#pragma unroll
    for (int j = 0; j < 4; j++)
        t[ty + 8 * j][tx] = W[(size_t)(k0 + ty + 8 * j) * C_ + c0 + tx];
    __syncthreads();
#pragma unroll
    for (int j = 0; j < 4; j++)
        Wt[(size_t)(c0 + ty + 8 * j) * C_ + k0 + tx] = rna_tf32(t[tx][ty + 8 * j]);
}

// ---------------- tf32 mma.sync TN GEMM: D = A[M,K] @ B[N,K]^T -------------------
// 128x128 CTA tile, 8 warps of 64x32, kc=32, 4-stage cp.async ring.
#define NSTAGE 4
#define SM_A 0
#define SM_B (NSTAGE*16384)
#define GSMEM (2*NSTAGE*16384)   // 128 KB

// swizzled smem byte offset of element (row, k) in a [128][32]-float stage
__device__ __forceinline__ uint32_t sa(int row, int k) {
    return (uint32_t)(row * 128 + ((k * 4) ^ ((row & 7) << 4)));
}

template<bool BIAS, bool RES, bool TRANS, bool ROUND>
__global__ __launch_bounds__(256, 1) void gemm_mma(
    const float* __restrict__ A, const float* __restrict__ B,
    const float* __restrict__ bias, const float* __restrict__ res,
    float* __restrict__ C, int lda, int ldb, int ldc, int K,
    long sA, long sB, long sC, float scale)
{
    extern __shared__ char smem[];
    const uint32_t sb = smem_u32(smem);
    const int tid = threadIdx.x, wid = tid >> 5, lane = tid & 31;
    const int gid = lane >> 2, tig = lane & 3;
    const int row0 = blockIdx.y * 128, col0 = blockIdx.x * 128;
    const int wm = (wid & 1) * 64, wn = (wid >> 1) * 32;
    const float* Ab = A + (size_t)blockIdx.z * sA;
    const float* Bb = B + (size_t)blockIdx.z * sB;
    float* Cb = C + (size_t)blockIdx.z * sC;

    float acc[4][4][4];
#pragma unroll
    for (int i = 0; i < 4; i++)
#pragma unroll
        for (int j = 0; j < 4; j++)
#pragma unroll
            for (int e = 0; e < 4; e++) acc[i][j][e] = 0.f;

    const int nk = K >> 5;

    auto load_chunk = [&](int ck) {
        int st = ck & (NSTAGE - 1);
        uint32_t ab = sb + SM_A + st * 16384;
        uint32_t bbs = sb + SM_B + st * 16384;
        int k0 = ck * 32;
#pragma unroll
        for (int j = 0; j < 4; j++) {
            int s = tid + 256 * j;          // 0..1023
            int r = s >> 3, seg = s & 7;
            uint32_t off = SWZ128((uint32_t)(r * 128 + seg * 16));
            cp16(ab + off, Ab + (size_t)(row0 + r) * lda + k0 + seg * 4);
            cp16(bbs + off, Bb + (size_t)(col0 + r) * ldb + k0 + seg * 4);
        }
    };

    // prologue
#pragma unroll
    for (int p = 0; p < NSTAGE - 1; p++) {
        if (p < nk) load_chunk(p);
        asm volatile("cp.async.commit_group;" ::: "memory");
    }

    for (int i = 0; i < nk; i++) {
        asm volatile("cp.async.wait_group %0;" :: "n"(NSTAGE - 2) : "memory");
        __syncthreads();
        if (i + NSTAGE - 1 < nk) load_chunk(i + NSTAGE - 1);
        asm volatile("cp.async.commit_group;" ::: "memory");

        int st = i & (NSTAGE - 1);
        uint32_t as = sb + SM_A + st * 16384;
        uint32_t bs = sb + SM_B + st * 16384;
#pragma unroll
        for (int k8 = 0; k8 < 4; k8++) {
            const int kb = k8 * 8;
            float af[4][4], bf[4][2];
#pragma unroll
            for (int mi = 0; mi < 4; mi++) {
                int r = wm + mi * 16 + gid;
                af[mi][0] = lds32(as + sa(r,     kb + tig));
                af[mi][1] = lds32(as + sa(r + 8, kb + tig));
                af[mi][2] = lds32(as + sa(r,     kb + tig + 4));
                af[mi][3] = lds32(as + sa(r + 8, kb + tig + 4));
            }
#pragma unroll
            for (int ni = 0; ni < 4; ni++) {
                int c = wn + ni * 8 + gid;
                bf[ni][0] = lds32(bs + sa(c, kb + tig));
                bf[ni][1] = lds32(bs + sa(c, kb + tig + 4));
            }
#pragma unroll
            for (int mi = 0; mi < 4; mi++)
#pragma unroll
                for (int ni = 0; ni < 4; ni++)
                    mma1688(acc[mi][ni], af[mi], bf[ni]);
        }
    }

    // epilogue: acc fragment c0,c1 at (row=gid, col=tig*2,+1); c2,c3 at row+8
#pragma unroll
    for (int mi = 0; mi < 4; mi++) {
#pragma unroll
        for (int ni = 0; ni < 4; ni++) {
            int r0 = row0 + wm + mi * 16 + gid;
            int c = col0 + wn + ni * 8 + tig * 2;
#pragma unroll
            for (int h = 0; h < 2; h++) {
                int r = r0 + h * 8;
                float v0 = acc[mi][ni][h * 2 + 0] * scale;
                float v1 = acc[mi][ni][h * 2 + 1] * scale;
                if (BIAS) {
                    float2 bb = *(const float2*)(bias + c);
                    v0 += bb.x; v1 += bb.y;
                }
                if (RES) {
                    float2 rr = *(const float2*)(res + (size_t)r * ldc + c);
                    v0 += rr.x; v1 += rr.y;
                }
                if (ROUND) { v0 = rna_tf32(v0); v1 = rna_tf32(v1); }
                if (TRANS) {
                    Cb[(size_t)(c)     * ldc + r] = v0;
                    Cb[(size_t)(c + 1) * ldc + r] = v1;
                } else {
                    *(float2*)(Cb + (size_t)r * ldc + c) = make_float2(v0, v1);
                }
            }
        }
    }
}

// ---------------- row softmax over 4096 (tf32-rounded output) -------------------
__global__ __launch_bounds__(256) void softmax4096(float* __restrict__ S) {
    float* row = S + (size_t)blockIdx.x * 4096;
    int t = threadIdx.x;
    float4 v[4];
#pragma unroll
    for (int i = 0; i < 4; i++) v[i] = ((const float4*)row)[t + 256 * i];

    float m = -1e30f;
#pragma unroll
    for (int i = 0; i < 4; i++)
        m = fmaxf(m, fmaxf(fmaxf(v[i].x, v[i].y), fmaxf(v[i].z, v[i].w)));
#pragma unroll
    for (int o = 16; o > 0; o >>= 1) m = fmaxf(m, __shfl_xor_sync(0xffffffffu, m, o));
    __shared__ float sm[8];
    if ((t & 31) == 0) sm[t >> 5] = m;
    __syncthreads();
    float bm = sm[0];
#pragma unroll
    for (int i = 1; i < 8; i++) bm = fmaxf(bm, sm[i]);

    float sum = 0.f;
#pragma unroll
    for (int i = 0; i < 4; i++) {
        v[i].x = __expf(v[i].x - bm); sum += v[i].x;
        v[i].y = __expf(v[i].y - bm); sum += v[i].y;
        v[i].z = __expf(v[i].z - bm); sum += v[i].z;
        v[i].w = __expf(v[i].w - bm); sum += v[i].w;
    }
#pragma unroll
    for (int o = 16; o > 0; o >>= 1) sum += __shfl_xor_sync(0xffffffffu, sum, o);
    __shared__ float ss[8];
    if ((t & 31) == 0) ss[t >> 5] = sum;
    __syncthreads();
    float tot = 0.f;
#pragma unroll
    for (int i = 0; i < 8; i++) tot += ss[i];
    float inv = 1.f / tot;
#pragma unroll
    for (int i = 0; i < 4; i++) {
        v[i].x = rna_tf32(v[i].x * inv);
        v[i].y = rna_tf32(v[i].y * inv);
        v[i].z = rna_tf32(v[i].z * inv);
        v[i].w = rna_tf32(v[i].w * inv);
        ((float4*)row)[t + 256 * i] = v[i];
    }
}

// -------------------------------- launch ---------------------------------------
extern "C" void kernel_launch(void* const* d_in, const int* in_sizes, int n_in,
                              void* d_out, int out_size) {
    const float* x     = (const float*)d_in[0];
    const float* gamma = (const float*)d_in[1];
    const float* beta  = (const float*)d_in[2];
    const float* Wq    = (const float*)d_in[3];
    const float* bq    = (const float*)d_in[4];
    const float* Wk    = (const float*)d_in[5];
    const float* bk    = (const float*)d_in[6];
    const float* Wv    = (const float*)d_in[7];
    const float* bv    = (const float*)d_in[8];
    const float* Wp    = (const float*)d_in[9];
    const float* bp    = (const float*)d_in[10];
    float* out = (float*)d_out;
    (void)in_sizes; (void)n_in; (void)out_size;

    float *xn, *q, *k, *vT, *o, *attn, *wt;
    cudaGetSymbolAddress((void**)&xn,   g_xn);
    cudaGetSymbolAddress((void**)&q,    g_q);
    cudaGetSymbolAddress((void**)&k,    g_k);
    cudaGetSymbolAddress((void**)&vT,   g_vT);
    cudaGetSymbolAddress((void**)&o,    g_o);
    cudaGetSymbolAddress((void**)&attn, g_attn);
    cudaGetSymbolAddress((void**)&wt,   g_wt);
    float* wtq = wt;
    float* wtk = wt + C_*C_;
    float* wtv = wt + 2*C_*C_;
    float* wtp = wt + 3*C_*C_;

    cudaFuncSetAttribute(gemm_mma<true,false,false,true>,  cudaFuncAttributeMaxDynamicSharedMemorySize, GSMEM);
    cudaFuncSetAttribute(gemm_mma<true,false,true,true>,   cudaFuncAttributeMaxDynamicSharedMemorySize, GSMEM);
    cudaFuncSetAttribute(gemm_mma<false,false,false,false>,cudaFuncAttributeMaxDynamicSharedMemorySize, GSMEM);
    cudaFuncSetAttribute(gemm_mma<false,false,false,true>, cudaFuncAttributeMaxDynamicSharedMemorySize, GSMEM);
    cudaFuncSetAttribute(gemm_mma<true,true,false,false>,  cudaFuncAttributeMaxDynamicSharedMemorySize, GSMEM);

    // GroupNorm (xn rounded to tf32; serves as GEMM input and residual)
    gn_stats<<<B_ * GRP, 1024>>>(x);
    gn_norm<<<(ROWS_TOT * C_ / 4) / 256, 256>>>(x, gamma, beta);

    // weight transposes (rounded to tf32)
    dim3 tb(32, 8), tg(8, 8);
    transposeW<<<tg, tb>>>(Wq, wtq);
    transposeW<<<tg, tb>>>(Wk, wtk);
    transposeW<<<tg, tb>>>(Wv, wtv);
    transposeW<<<tg, tb>>>(Wp, wtp);

    // QKV projections: D[16384,256] = xn @ W^T(+b)
    dim3 gQKV(2, 128, 1);
    gemm_mma<true,false,false,true><<<gQKV, 256, GSMEM>>>(
        xn, wtq, bq, nullptr, q, C_, C_, C_, C_, 0, 0, 0, 1.f);
    gemm_mma<true,false,false,true><<<gQKV, 256, GSMEM>>>(
        xn, wtk, bk, nullptr, k, C_, C_, C_, C_, 0, 0, 0, 1.f);
    gemm_mma<true,false,true,true><<<gQKV, 256, GSMEM>>>(
        xn, wtv, bv, nullptr, vT, C_, C_, ROWS_TOT, C_, 0, 0, 0, 1.f);

    // logits S = (Q @ K^T) * C^-0.5, batched
    dim3 gQK(32, 32, B_);
    gemm_mma<false,false,false,false><<<gQK, 256, GSMEM>>>(
        q, k, nullptr, nullptr, attn, C_, C_, NTOK, C_,
        (long)NTOK * C_, (long)NTOK * C_, (long)NTOK * NTOK, 0.0625f);

    // softmax (writes tf32-rounded P)
    softmax4096<<<B_ * NTOK, 256>>>(attn);

    // O = P @ V  (B operand = V^T, K-major)
    dim3 gAV(2, 32, B_);
    gemm_mma<false,false,false,true><<<gAV, 256, GSMEM>>>(
        attn, vT, nullptr, nullptr, o, NTOK, ROWS_TOT, C_, NTOK,
        (long)NTOK * NTOK, (long)NTOK, (long)NTOK * C_, 1.f);

    // final projection + bias + residual -> d_out (fp32)
    gemm_mma<true,true,false,false><<<gQKV, 256, GSMEM>>>(
        o, wtp, bp, xn, out, C_, C_, C_, C_, 0, 0, 0, 1.f);
}

// round 7
// speedup vs baseline: 3.0468x; 1.1026x over previous
#include <cuda_runtime.h>
#include <cstdint>
#include <math.h>

// Problem constants: B=4, H=W=64 -> N=4096 tokens, C=256, GROUPS=8
#define B_ 4
#define NTOK 4096
#define C_ 256
#define GRP 8
#define CG 32
#define ROWS_TOT (B_*NTOK)   // 16384

// ---------------- scratch (device globals) ------------------------------------
__device__ float2 g_part[32*8];         // groupnorm partial (sum, sumsq)
__device__ float g_mean[B_*GRP];
__device__ float g_rstd[B_*GRP];
__device__ float g_xn[ROWS_TOT*C_];     // normalized input (tf32-rounded), residual
__device__ float g_qk[ROWS_TOT*512];    // q (cols 0-255) and k (cols 256-511)
__device__ float g_vT[ROWS_TOT*C_];     // V transposed: [C_][ROWS_TOT]
__device__ float g_o[ROWS_TOT*C_];
__device__ float g_wt[4*C_*C_];         // transposed weights: wtq wtk wtv wtp
__device__ float g_attn[(size_t)B_*NTOK*NTOK];  // unnormalized exp(QK^T/16)

// ---------------- helpers -------------------------------------------------------
__device__ __forceinline__ uint32_t smem_u32(const void* p) {
    uint32_t a;
    asm("{ .reg .u64 t; cvta.to.shared.u64 t, %1; cvt.u32.u64 %0, t; }" : "=r"(a) : "l"(p));
    return a;
}
__device__ __forceinline__ float rna_tf32(float x) {
    uint32_t r; asm("cvt.rna.tf32.f32 %0, %1;" : "=r"(r) : "f"(x));
    return __uint_as_float(r);
}
__device__ __forceinline__ void cp16(uint32_t dst, const void* src) {
    asm volatile("cp.async.cg.shared.global [%0], [%1], 16;" :: "r"(dst), "l"(src));
}
__device__ __forceinline__ float lds32(uint32_t a) {
    float v; asm volatile("ld.shared.f32 %0, [%1];" : "=f"(v) : "r"(a));
    return v;
}
#define SWZ128(o) ((o) ^ (((o) >> 3) & 0x70))

// m16n8k8 tf32 MMA, fp32 accumulate (portable HMMA; tcgen05 rejected by the
// harness's compute_103 PTX target).
__device__ __forceinline__ void mma1688(float* d, const float* a, const float* b) {
    asm volatile(
        "mma.sync.aligned.m16n8k8.row.col.f32.tf32.tf32.f32 "
        "{%0,%1,%2,%3}, {%4,%5,%6,%7}, {%8,%9}, {%0,%1,%2,%3};"
        : "+f"(d[0]), "+f"(d[1]), "+f"(d[2]), "+f"(d[3])
        : "r"(__float_as_uint(a[0])), "r"(__float_as_uint(a[1])),
          "r"(__float_as_uint(a[2])), "r"(__float_as_uint(a[3])),
          "r"(__float_as_uint(b[0])), "r"(__float_as_uint(b[1])));
}

// ---------------- GroupNorm partial stats: grid (32, 8) -------------------------
__global__ __launch_bounds__(256) void gn_part(const float* __restrict__ x) {
    int bg = blockIdx.x, slice = blockIdx.y;
    int b = bg >> 3, g = bg & 7;
    const float* xb = x + (size_t)b * NTOK * C_ + g * CG + (size_t)slice * 512 * C_;
    float s = 0.f, ss = 0.f;
    for (int i = threadIdx.x; i < 512 * CG; i += 256) {
        int n = i >> 5, c = i & 31;
        float v = __ldg(&xb[(size_t)n * C_ + c]);
        s += v; ss += v * v;
    }
    __shared__ float sh1[256], sh2[256];
    int t = threadIdx.x;
    sh1[t] = s; sh2[t] = ss;
    __syncthreads();
    for (int o = 128; o > 0; o >>= 1) {
        if (t < o) { sh1[t] += sh1[t + o]; sh2[t] += sh2[t + o]; }
        __syncthreads();
    }
    if (t == 0) g_part[bg * 8 + slice] = make_float2(sh1[0], sh2[0]);
}

__global__ __launch_bounds__(32) void gn_comb() {
    int bg = threadIdx.x;
    float s = 0.f, ss = 0.f;
#pragma unroll
    for (int i = 0; i < 8; i++) {
        float2 p = g_part[bg * 8 + i];
        s += p.x; ss += p.y;
    }
    float inv = 1.f / (float)(NTOK * CG);
    float m = s * inv;
    float var = ss * inv - m * m;
    g_mean[bg] = m;
    g_rstd[bg] = rsqrtf(var + 1e-3f);
}

// ---------------- GroupNorm apply (tf32-rounded output) -------------------------
__global__ __launch_bounds__(256) void gn_norm(const float* __restrict__ x,
                                               const float* __restrict__ gamma,
                                               const float* __restrict__ beta) {
    size_t i4 = (size_t)blockIdx.x * blockDim.x + threadIdx.x;
    size_t i = i4 * 4;
    int c = (int)(i & (C_ - 1));
    size_t row = i >> 8;
    int b = (int)(row >> 12);
    int bg = b * GRP + (c >> 5);
    float m = g_mean[bg], r = g_rstd[bg];
    float4 xv = ((const float4*)x)[i4];
    float4 gv = *(const float4*)(gamma + c);
    float4 bv = *(const float4*)(beta + c);
    float4 o;
    o.x = rna_tf32((xv.x - m) * r * gv.x + bv.x);
    o.y = rna_tf32((xv.y - m) * r * gv.y + bv.y);
    o.z = rna_tf32((xv.z - m) * r * gv.z + bv.z);
    o.w = rna_tf32((xv.w - m) * r * gv.w + bv.w);
    ((float4*)g_xn)[i4] = o;
}

// ---------------- 4-way weight transpose (rounded to tf32) ----------------------
__global__ __launch_bounds__(256) void transposeW4(
    const float* __restrict__ W0, const float* __restrict__ W1,
    const float* __restrict__ W2, const float* __restrict__ W3,
    float* __restrict__ wt)
{
    const float* W = (blockIdx.z == 0) ? W0 : (blockIdx.z == 1) ? W1
                     : (blockIdx.z == 2) ? W2 : W3;
    float* Wt = wt + (size_t)blockIdx.z * C_ * C_;
    __shared__ float t[32][33];
    int c0 = blockIdx.x * 32, k0 = blockIdx.y * 32;
    int tx = threadIdx.x & 31, ty = threadIdx.x >> 5;
#pragma unroll
    for (int j = 0; j < 4; j++)
        t[ty + 8 * j][tx] = W[(size_t)(k0 + ty + 8 * j) * C_ + c0 + tx];
    __syncthreads();
#pragma unroll
    for (int j = 0; j < 4; j++)
        Wt[(size_t)(c0 + ty + 8 * j) * C_ + k0 + tx] = rna_tf32(t[tx][ty + 8 * j]);
}

// ---------------- tf32 mma.sync TN GEMM: D = A[M,K] @ B[N,K]^T -------------------
// 128x128 CTA tile, 8 warps of 64x32, kc=32, 4-stage cp.async ring.
// EXP: D = exp(acc*scale) (unnormalized softmax numerator).
// NORM: divide by row sums computed via an extra ones-column MMA (P @ 1).
#define NSTAGE 4
#define SM_A 0
#define SM_B (NSTAGE*16384)
#define GSMEM (2*NSTAGE*16384)   // 128 KB

// swizzled smem byte offset of element (row, k) in a [128][32]-float stage
__device__ __forceinline__ uint32_t sa(int row, int k) {
    return (uint32_t)(row * 128 + ((k * 4) ^ ((row & 7) << 4)));
}

template<bool BIAS, bool RES, bool TRANS, bool ROUND, bool EXP, bool NORM>
__global__ __launch_bounds__(256, 1) void gemm_mma(
    const float* __restrict__ A, const float* __restrict__ B,
    const float* __restrict__ bias, const float* __restrict__ bias2,
    const float* __restrict__ res,
    float* __restrict__ C, int lda, int ldb, int ldc, int K, int bias_split,
    long sA, long sB, long sC, float scale)
{
    extern __shared__ char smem[];
    const uint32_t sb = smem_u32(smem);
    const int tid = threadIdx.x, wid = tid >> 5, lane = tid & 31;
    const int gid = lane >> 2, tig = lane & 3;
    const int row0 = blockIdx.y * 128, col0 = blockIdx.x * 128;
    const int wm = (wid & 1) * 64, wn = (wid >> 1) * 32;
    const float* Ab = A + (size_t)blockIdx.z * sA;
    const float* Bb = B + (size_t)blockIdx.z * sB;
    float* Cb = C + (size_t)blockIdx.z * sC;

    float acc[4][4][4];
#pragma unroll
    for (int i = 0; i < 4; i++)
#pragma unroll
        for (int j = 0; j < 4; j++)
#pragma unroll
            for (int e = 0; e < 4; e++) acc[i][j][e] = 0.f;

    float aones[4][4];
    if (NORM) {
#pragma unroll
        for (int i = 0; i < 4; i++)
#pragma unroll
            for (int e = 0; e < 4; e++) aones[i][e] = 0.f;
    }

    const int nk = K >> 5;

    auto load_chunk = [&](int ck) {
        int st = ck & (NSTAGE - 1);
        uint32_t ab = sb + SM_A + st * 16384;
        uint32_t bbs = sb + SM_B + st * 16384;
        int k0 = ck * 32;
#pragma unroll
        for (int j = 0; j < 4; j++) {
            int s = tid + 256 * j;          // 0..1023
            int r = s >> 3, seg = s & 7;
            uint32_t off = SWZ128((uint32_t)(r * 128 + seg * 16));
            cp16(ab + off, Ab + (size_t)(row0 + r) * lda + k0 + seg * 4);
            cp16(bbs + off, Bb + (size_t)(col0 + r) * ldb + k0 + seg * 4);
        }
    };

    // prologue
#pragma unroll
    for (int p = 0; p < NSTAGE - 1; p++) {
        if (p < nk) load_chunk(p);
        asm volatile("cp.async.commit_group;" ::: "memory");
    }

    for (int i = 0; i < nk; i++) {
        asm volatile("cp.async.wait_group %0;" :: "n"(NSTAGE - 2) : "memory");
        __syncthreads();
        if (i + NSTAGE - 1 < nk) load_chunk(i + NSTAGE - 1);
        asm volatile("cp.async.commit_group;" ::: "memory");

        int st = i & (NSTAGE - 1);
        uint32_t as = sb + SM_A + st * 16384;
        uint32_t bs = sb + SM_B + st * 16384;
#pragma unroll
        for (int k8 = 0; k8 < 4; k8++) {
            const int kb = k8 * 8;
            float af[4][4], bf[4][2];
#pragma unroll
            for (int mi = 0; mi < 4; mi++) {
                int r = wm + mi * 16 + gid;
                af[mi][0] = lds32(as + sa(r,     kb + tig));
                af[mi][1] = lds32(as + sa(r + 8, kb + tig));
                af[mi][2] = lds32(as + sa(r,     kb + tig + 4));
                af[mi][3] = lds32(as + sa(r + 8, kb + tig + 4));
            }
#pragma unroll
            for (int ni = 0; ni < 4; ni++) {
                int c = wn + ni * 8 + gid;
                bf[ni][0] = lds32(bs + sa(c, kb + tig));
                bf[ni][1] = lds32(bs + sa(c, kb + tig + 4));
            }
#pragma unroll
            for (int mi = 0; mi < 4; mi++)
#pragma unroll
                for (int ni = 0; ni < 4; ni++)
                    mma1688(acc[mi][ni], af[mi], bf[ni]);
            if (NORM) {
                const float onesb[2] = {1.f, 1.f};
#pragma unroll
                for (int mi = 0; mi < 4; mi++)
                    mma1688(aones[mi], af[mi], onesb);
            }
        }
    }

    // epilogue: acc fragment c0,c1 at (row=gid, col=tig*2,+1); c2,c3 at row+8
#pragma unroll
    for (int mi = 0; mi < 4; mi++) {
#pragma unroll
        for (int ni = 0; ni < 4; ni++) {
            int r0 = row0 + wm + mi * 16 + gid;
            int c = col0 + wn + ni * 8 + tig * 2;
#pragma unroll
            for (int h = 0; h < 2; h++) {
                int r = r0 + h * 8;
                float v0 = acc[mi][ni][h * 2 + 0] * scale;
                float v1 = acc[mi][ni][h * 2 + 1] * scale;
                if (NORM) {
                    float inv = 1.f / aones[mi][h * 2];
                    v0 *= inv; v1 *= inv;
                }
                if (EXP) { v0 = __expf(v0); v1 = __expf(v1); }
                if (BIAS) {
                    if (bias2 && c >= bias_split) {
                        float2 bb = *(const float2*)(bias2 + (c - bias_split));
                        v0 += bb.x; v1 += bb.y;
                    } else {
                        float2 bb = *(const float2*)(bias + c);
                        v0 += bb.x; v1 += bb.y;
                    }
                }
                if (RES) {
                    float2 rr = *(const float2*)(res + (size_t)r * ldc + c);
                    v0 += rr.x; v1 += rr.y;
                }
                if (ROUND) { v0 = rna_tf32(v0); v1 = rna_tf32(v1); }
                if (TRANS) {
                    Cb[(size_t)(c)     * ldc + r] = v0;
                    Cb[(size_t)(c + 1) * ldc + r] = v1;
                } else {
                    *(float2*)(Cb + (size_t)r * ldc + c) = make_float2(v0, v1);
                }
            }
        }
    }
}

// -------------------------------- launch ---------------------------------------
extern "C" void kernel_launch(void* const* d_in, const int* in_sizes, int n_in,
                              void* d_out, int out_size) {
    const float* x     = (const float*)d_in[0];
    const float* gamma = (const float*)d_in[1];
    const float* beta  = (const float*)d_in[2];
    const float* Wq    = (const float*)d_in[3];
    const float* bq    = (const float*)d_in[4];
    const float* Wk    = (const float*)d_in[5];
    const float* bk    = (const float*)d_in[6];
    const float* Wv    = (const float*)d_in[7];
    const float* bv    = (const float*)d_in[8];
    const float* Wp    = (const float*)d_in[9];
    const float* bp    = (const float*)d_in[10];
    float* out = (float*)d_out;
    (void)in_sizes; (void)n_in; (void)out_size;

    float *xn, *qk, *vT, *o, *attn, *wt;
    cudaGetSymbolAddress((void**)&xn,   g_xn);
    cudaGetSymbolAddress((void**)&qk,   g_qk);
    cudaGetSymbolAddress((void**)&vT,   g_vT);
    cudaGetSymbolAddress((void**)&o,    g_o);
    cudaGetSymbolAddress((void**)&attn, g_attn);
    cudaGetSymbolAddress((void**)&wt,   g_wt);
    float* wtqk = wt;                 // wtq then wtk: 512 rows of 256
    float* wtv  = wt + 2*C_*C_;
    float* wtp  = wt + 3*C_*C_;

    cudaFuncSetAttribute(gemm_mma<true,false,false,true,false,false>,  cudaFuncAttributeMaxDynamicSharedMemorySize, GSMEM);
    cudaFuncSetAttribute(gemm_mma<true,false,true,true,false,false>,   cudaFuncAttributeMaxDynamicSharedMemorySize, GSMEM);
    cudaFuncSetAttribute(gemm_mma<false,false,false,true,true,false>,  cudaFuncAttributeMaxDynamicSharedMemorySize, GSMEM);
    cudaFuncSetAttribute(gemm_mma<false,false,false,true,false,true>,  cudaFuncAttributeMaxDynamicSharedMemorySize, GSMEM);
    cudaFuncSetAttribute(gemm_mma<true,true,false,false,false,false>,  cudaFuncAttributeMaxDynamicSharedMemorySize, GSMEM);

    // launch idx:                                         (ncu -s 5 -c 1 captures idx 5)
    // 0 gn_part, 1 gn_comb, 2 gn_norm, 3 transposeW4, 4 qkProj, 5 QKT, 6 vProj, 7 PV, 8 outProj
    dim3 gp(32, 8);
    gn_part<<<gp, 256>>>(x);
    gn_comb<<<1, 32>>>();
    gn_norm<<<(ROWS_TOT * C_ / 4) / 256, 256>>>(x, gamma, beta);

    dim3 tg(8, 8, 4);
    transposeW4<<<tg, 256>>>(Wq, Wk, Wv, Wp, wt);

    // fused Q+K projection: [16384,256] @ [256,512] + [bq|bk] -> g_qk
    dim3 gQK(4, 128, 1);
    gemm_mma<true,false,false,true,false,false><<<gQK, 256, GSMEM>>>(
        xn, wtqk, bq, bk, nullptr, qk, C_, C_, 512, C_, 256, 0, 0, 0, 1.f);

    // E = exp((Q @ K^T) * C^-0.5), batched, unnormalized
    dim3 gS(32, 32, B_);
    gemm_mma<false,false,false,true,true,false><<<gS, 256, GSMEM>>>(
        qk, qk + 256, nullptr, nullptr, nullptr, attn, 512, 512, NTOK, C_, 0,
        (long)NTOK * 512, (long)NTOK * 512, (long)NTOK * NTOK, 0.0625f);

    // V projection -> vT [C][16384]
    dim3 gV(2, 128, 1);
    gemm_mma<true,false,true,true,false,false><<<gV, 256, GSMEM>>>(
        xn, wtv, bv, nullptr, nullptr, vT, C_, C_, ROWS_TOT, C_, 0, 0, 0, 0, 1.f);

    // O = (E @ V) / rowsum(E)  (row sums via ones-MMA)
    dim3 gAV(2, 32, B_);
    gemm_mma<false,false,false,true,false,true><<<gAV, 256, GSMEM>>>(
        attn, vT, nullptr, nullptr, nullptr, o, NTOK, ROWS_TOT, C_, NTOK, 0,
        (long)NTOK * NTOK, (long)NTOK, (long)NTOK * C_, 1.f);

    // final projection + bias + residual -> d_out (fp32)
    gemm_mma<true,true,false,false,false,false><<<gV, 256, GSMEM>>>(
        o, wtp, bp, nullptr, xn, out, C_, C_, C_, C_, 0, 0, 0, 0, 1.f);
}

// round 8
// speedup vs baseline: 3.5547x; 1.1667x over previous
#include <cuda_runtime.h>
#include <cstdint>
#include <math.h>

// Problem constants: B=4, H=W=64 -> N=4096 tokens, C=256, GROUPS=8
#define B_ 4
#define NTOK 4096
#define C_ 256
#define GRP 8
#define CG 32
#define ROWS_TOT (B_*NTOK)   // 16384

// ---------------- scratch (device globals) ------------------------------------
__device__ float2 g_part[32*8];         // groupnorm partial (sum, sumsq)
__device__ float g_mean[B_*GRP];
__device__ float g_rstd[B_*GRP];
__device__ float g_xn[ROWS_TOT*C_];     // normalized input (tf32-rounded), residual
__device__ float g_qk[ROWS_TOT*512];    // q (cols 0-255) and k (cols 256-511)
__device__ float g_vT[ROWS_TOT*C_];     // V transposed: [C_][ROWS_TOT]
__device__ float g_o[ROWS_TOT*C_];
__device__ float g_wt[4*C_*C_];         // transposed weights: wtq wtk wtv wtp
__device__ float g_attn[(size_t)B_*NTOK*NTOK];  // unnormalized exp(QK^T/16)

// ---------------- helpers -------------------------------------------------------
__device__ __forceinline__ uint32_t smem_u32(const void* p) {
    uint32_t a;
    asm("{ .reg .u64 t; cvta.to.shared.u64 t, %1; cvt.u32.u64 %0, t; }" : "=r"(a) : "l"(p));
    return a;
}
__device__ __forceinline__ float rna_tf32(float x) {
    uint32_t r; asm("cvt.rna.tf32.f32 %0, %1;" : "=r"(r) : "f"(x));
    return __uint_as_float(r);
}
__device__ __forceinline__ void cp16(uint32_t dst, const void* src) {
    asm volatile("cp.async.cg.shared.global [%0], [%1], 16;" :: "r"(dst), "l"(src));
}
__device__ __forceinline__ float lds32(uint32_t a) {
    float v; asm volatile("ld.shared.f32 %0, [%1];" : "=f"(v) : "r"(a));
    return v;
}
#define SWZ128(o) ((o) ^ (((o) >> 3) & 0x70))

// m16n8k8 tf32 MMA, fp32 accumulate (portable HMMA; tcgen05 rejected by the
// harness's compute_103 PTX target).
__device__ __forceinline__ void mma1688(float* d, const float* a, const float* b) {
    asm volatile(
        "mma.sync.aligned.m16n8k8.row.col.f32.tf32.tf32.f32 "
        "{%0,%1,%2,%3}, {%4,%5,%6,%7}, {%8,%9}, {%0,%1,%2,%3};"
        : "+f"(d[0]), "+f"(d[1]), "+f"(d[2]), "+f"(d[3])
        : "r"(__float_as_uint(a[0])), "r"(__float_as_uint(a[1])),
          "r"(__float_as_uint(a[2])), "r"(__float_as_uint(a[3])),
          "r"(__float_as_uint(b[0])), "r"(__float_as_uint(b[1])));
}

// ---------------- GroupNorm partial stats: grid (32, 8) -------------------------
__global__ __launch_bounds__(256) void gn_part(const float* __restrict__ x) {
    int bg = blockIdx.x, slice = blockIdx.y;
    int b = bg >> 3, g = bg & 7;
    const float* xb = x + (size_t)b * NTOK * C_ + g * CG + (size_t)slice * 512 * C_;
    float s = 0.f, ss = 0.f;
    for (int i = threadIdx.x; i < 512 * CG; i += 256) {
        int n = i >> 5, c = i & 31;
        float v = __ldg(&xb[(size_t)n * C_ + c]);
        s += v; ss += v * v;
    }
    __shared__ float sh1[256], sh2[256];
    int t = threadIdx.x;
    sh1[t] = s; sh2[t] = ss;
    __syncthreads();
    for (int o = 128; o > 0; o >>= 1) {
        if (t < o) { sh1[t] += sh1[t + o]; sh2[t] += sh2[t + o]; }
        __syncthreads();
    }
    if (t == 0) g_part[bg * 8 + slice] = make_float2(sh1[0], sh2[0]);
}

__global__ __launch_bounds__(32) void gn_comb() {
    int bg = threadIdx.x;
    float s = 0.f, ss = 0.f;
#pragma unroll
    for (int i = 0; i < 8; i++) {
        float2 p = g_part[bg * 8 + i];
        s += p.x; ss += p.y;
    }
    float inv = 1.f / (float)(NTOK * CG);
    float m = s * inv;
    float var = ss * inv - m * m;
    g_mean[bg] = m;
    g_rstd[bg] = rsqrtf(var + 1e-3f);
}

// ---------------- GroupNorm apply (tf32-rounded output) -------------------------
__global__ __launch_bounds__(256) void gn_norm(const float* __restrict__ x,
                                               const float* __restrict__ gamma,
                                               const float* __restrict__ beta) {
    size_t i4 = (size_t)blockIdx.x * blockDim.x + threadIdx.x;
    size_t i = i4 * 4;
    int c = (int)(i & (C_ - 1));
    size_t row = i >> 8;
    int b = (int)(row >> 12);
    int bg = b * GRP + (c >> 5);
    float m = g_mean[bg], r = g_rstd[bg];
    float4 xv = ((const float4*)x)[i4];
    float4 gv = *(const float4*)(gamma + c);
    float4 bv = *(const float4*)(beta + c);
    float4 o;
    o.x = rna_tf32((xv.x - m) * r * gv.x + bv.x);
    o.y = rna_tf32((xv.y - m) * r * gv.y + bv.y);
    o.z = rna_tf32((xv.z - m) * r * gv.z + bv.z);
    o.w = rna_tf32((xv.w - m) * r * gv.w + bv.w);
    ((float4*)g_xn)[i4] = o;
}

// ---------------- 4-way weight transpose (rounded to tf32) ----------------------
__global__ __launch_bounds__(256) void transposeW4(
    const float* __restrict__ W0, const float* __restrict__ W1,
    const float* __restrict__ W2, const float* __restrict__ W3,
    float* __restrict__ wt)
{
    const float* W = (blockIdx.z == 0) ? W0 : (blockIdx.z == 1) ? W1
                     : (blockIdx.z == 2) ? W2 : W3;
    float* Wt = wt + (size_t)blockIdx.z * C_ * C_;
    __shared__ float t[32][33];
    int c0 = blockIdx.x * 32, k0 = blockIdx.y * 32;
    int tx = threadIdx.x & 31, ty = threadIdx.x >> 5;
#pragma unroll
    for (int j = 0; j < 4; j++)
        t[ty + 8 * j][tx] = W[(size_t)(k0 + ty + 8 * j) * C_ + c0 + tx];
    __syncthreads();
#pragma unroll
    for (int j = 0; j < 4; j++)
        Wt[(size_t)(c0 + ty + 8 * j) * C_ + k0 + tx] = rna_tf32(t[tx][ty + 8 * j]);
}

// ---------------- tf32 mma.sync TN GEMM: D = A[M,K] @ B[N,K]^T -------------------
// 128x128 CTA tile, 8 warps of 64x32, kc=32, 3-stage cp.async ring.
// 96 KB smem/CTA -> 2 CTAs/SM (16 warps) for latency hiding.
// EXP: D = exp(acc*scale). NORM: divide by row sums accumulated from the
// A(=E) fragments in registers (exact softmax denominator).
#define NSTAGE 3
#define SM_A 0
#define SM_B (NSTAGE*16384)
#define GSMEM (2*NSTAGE*16384)   // 96 KB

// swizzled smem byte offset of element (row, k) in a [128][32]-float stage
__device__ __forceinline__ uint32_t sa(int row, int k) {
    return (uint32_t)(row * 128 + ((k * 4) ^ ((row & 7) << 4)));
}

template<bool BIAS, bool RES, bool TRANS, bool ROUND, bool EXP, bool NORM>
__global__ __launch_bounds__(256, 2) void gemm_mma(
    const float* __restrict__ A, const float* __restrict__ B,
    const float* __restrict__ bias, const float* __restrict__ bias2,
    const float* __restrict__ res,
    float* __restrict__ C, int lda, int ldb, int ldc, int K, int bias_split,
    long sA, long sB, long sC, float scale)
{
    extern __shared__ char smem[];
    const uint32_t sb = smem_u32(smem);
    const int tid = threadIdx.x, wid = tid >> 5, lane = tid & 31;
    const int gid = lane >> 2, tig = lane & 3;
    const int row0 = blockIdx.y * 128, col0 = blockIdx.x * 128;
    const int wm = (wid & 1) * 64, wn = (wid >> 1) * 32;
    const float* Ab = A + (size_t)blockIdx.z * sA;
    const float* Bb = B + (size_t)blockIdx.z * sB;
    float* Cb = C + (size_t)blockIdx.z * sC;

    float acc[4][4][4];
#pragma unroll
    for (int i = 0; i < 4; i++)
#pragma unroll
        for (int j = 0; j < 4; j++)
#pragma unroll
            for (int e = 0; e < 4; e++) acc[i][j][e] = 0.f;

    float rowpart[4][2];        // NORM: per-lane partial row sums of A(=E)
    if (NORM) {
#pragma unroll
        for (int i = 0; i < 4; i++) { rowpart[i][0] = 0.f; rowpart[i][1] = 0.f; }
    }

    const int nk = K >> 5;

    auto load_chunk = [&](int ck, int st) {
        uint32_t ab = sb + SM_A + st * 16384;
        uint32_t bbs = sb + SM_B + st * 16384;
        int k0 = ck * 32;
#pragma unroll
        for (int j = 0; j < 4; j++) {
            int s = tid + 256 * j;          // 0..1023
            int r = s >> 3, seg = s & 7;
            uint32_t off = SWZ128((uint32_t)(r * 128 + seg * 16));
            cp16(ab + off, Ab + (size_t)(row0 + r) * lda + k0 + seg * 4);
            cp16(bbs + off, Bb + (size_t)(col0 + r) * ldb + k0 + seg * 4);
        }
    };

    // prologue: NSTAGE-1 = 2 chunks in flight
#pragma unroll
    for (int p = 0; p < NSTAGE - 1; p++) {
        if (p < nk) load_chunk(p, p);
        asm volatile("cp.async.commit_group;" ::: "memory");
    }

    int st = 0, stl = NSTAGE - 1;   // compute stage, next load stage
    for (int i = 0; i < nk; i++) {
        asm volatile("cp.async.wait_group %0;" :: "n"(NSTAGE - 2) : "memory");
        __syncthreads();
        if (i + NSTAGE - 1 < nk) load_chunk(i + NSTAGE - 1, stl);
        asm volatile("cp.async.commit_group;" ::: "memory");

        uint32_t as = sb + SM_A + st * 16384;
        uint32_t bs = sb + SM_B + st * 16384;
#pragma unroll
        for (int k8 = 0; k8 < 4; k8++) {
            const int kb = k8 * 8;
            float af[4][4], bf[4][2];
#pragma unroll
            for (int mi = 0; mi < 4; mi++) {
                int r = wm + mi * 16 + gid;
                af[mi][0] = lds32(as + sa(r,     kb + tig));
                af[mi][1] = lds32(as + sa(r + 8, kb + tig));
                af[mi][2] = lds32(as + sa(r,     kb + tig + 4));
                af[mi][3] = lds32(as + sa(r + 8, kb + tig + 4));
            }
#pragma unroll
            for (int ni = 0; ni < 4; ni++) {
                int c = wn + ni * 8 + gid;
                bf[ni][0] = lds32(bs + sa(c, kb + tig));
                bf[ni][1] = lds32(bs + sa(c, kb + tig + 4));
            }
#pragma unroll
            for (int mi = 0; mi < 4; mi++)
#pragma unroll
                for (int ni = 0; ni < 4; ni++)
                    mma1688(acc[mi][ni], af[mi], bf[ni]);
            if (NORM) {
#pragma unroll
                for (int mi = 0; mi < 4; mi++) {
                    rowpart[mi][0] += af[mi][0] + af[mi][2];
                    rowpart[mi][1] += af[mi][1] + af[mi][3];
                }
            }
        }
        st = (st + 1 == NSTAGE) ? 0 : st + 1;
        stl = (stl + 1 == NSTAGE) ? 0 : stl + 1;
    }

    if (NORM) {
        // reduce partial row sums across the 4 lanes of each quad (k coverage)
#pragma unroll
        for (int mi = 0; mi < 4; mi++)
#pragma unroll
            for (int h = 0; h < 2; h++) {
                float s = rowpart[mi][h];
                s += __shfl_xor_sync(0xffffffffu, s, 1);
                s += __shfl_xor_sync(0xffffffffu, s, 2);
                rowpart[mi][h] = 1.f / s;
            }
    }

    // epilogue: acc fragment c0,c1 at (row=gid, col=tig*2,+1); c2,c3 at row+8
#pragma unroll
    for (int mi = 0; mi < 4; mi++) {
#pragma unroll
        for (int ni = 0; ni < 4; ni++) {
            int r0 = row0 + wm + mi * 16 + gid;
            int c = col0 + wn + ni * 8 + tig * 2;
#pragma unroll
            for (int h = 0; h < 2; h++) {
                int r = r0 + h * 8;
                float v0 = acc[mi][ni][h * 2 + 0] * scale;
                float v1 = acc[mi][ni][h * 2 + 1] * scale;
                if (NORM) {
                    float inv = rowpart[mi][h];
                    v0 *= inv; v1 *= inv;
                }
                if (EXP) { v0 = __expf(v0); v1 = __expf(v1); }
                if (BIAS) {
                    if (bias2 && c >= bias_split) {
                        float2 bb = *(const float2*)(bias2 + (c - bias_split));
                        v0 += bb.x; v1 += bb.y;
                    } else {
                        float2 bb = *(const float2*)(bias + c);
                        v0 += bb.x; v1 += bb.y;
                    }
                }
                if (RES) {
                    float2 rr = *(const float2*)(res + (size_t)r * ldc + c);
                    v0 += rr.x; v1 += rr.y;
                }
                if (ROUND) { v0 = rna_tf32(v0); v1 = rna_tf32(v1); }
                if (TRANS) {
                    Cb[(size_t)(c)     * ldc + r] = v0;
                    Cb[(size_t)(c + 1) * ldc + r] = v1;
                } else {
                    *(float2*)(Cb + (size_t)r * ldc + c) = make_float2(v0, v1);
                }
            }
        }
    }
}

// -------------------------------- launch ---------------------------------------
extern "C" void kernel_launch(void* const* d_in, const int* in_sizes, int n_in,
                              void* d_out, int out_size) {
    const float* x     = (const float*)d_in[0];
    const float* gamma = (const float*)d_in[1];
    const float* beta  = (const float*)d_in[2];
    const float* Wq    = (const float*)d_in[3];
    const float* bq    = (const float*)d_in[4];
    const float* Wk    = (const float*)d_in[5];
    const float* bk    = (const float*)d_in[6];
    const float* Wv    = (const float*)d_in[7];
    const float* bv    = (const float*)d_in[8];
    const float* Wp    = (const float*)d_in[9];
    const float* bp    = (const float*)d_in[10];
    float* out = (float*)d_out;
    (void)in_sizes; (void)n_in; (void)out_size;

    float *xn, *qk, *vT, *o, *attn, *wt;
    cudaGetSymbolAddress((void**)&xn,   g_xn);
    cudaGetSymbolAddress((void**)&qk,   g_qk);
    cudaGetSymbolAddress((void**)&vT,   g_vT);
    cudaGetSymbolAddress((void**)&o,    g_o);
    cudaGetSymbolAddress((void**)&attn, g_attn);
    cudaGetSymbolAddress((void**)&wt,   g_wt);
    float* wtqk = wt;                 // wtq then wtk: 512 rows of 256
    float* wtv  = wt + 2*C_*C_;
    float* wtp  = wt + 3*C_*C_;

    cudaFuncSetAttribute(gemm_mma<true,false,false,true,false,false>,  cudaFuncAttributeMaxDynamicSharedMemorySize, GSMEM);
    cudaFuncSetAttribute(gemm_mma<true,false,true,true,false,false>,   cudaFuncAttributeMaxDynamicSharedMemorySize, GSMEM);
    cudaFuncSetAttribute(gemm_mma<false,false,false,true,true,false>,  cudaFuncAttributeMaxDynamicSharedMemorySize, GSMEM);
    cudaFuncSetAttribute(gemm_mma<false,false,false,true,false,true>,  cudaFuncAttributeMaxDynamicSharedMemorySize, GSMEM);
    cudaFuncSetAttribute(gemm_mma<true,true,false,false,false,false>,  cudaFuncAttributeMaxDynamicSharedMemorySize, GSMEM);

    // 0 gn_part, 1 gn_comb, 2 gn_norm, 3 transposeW4, 4 qkProj, 5 QKT, 6 vProj, 7 PV, 8 outProj
    dim3 gp(32, 8);
    gn_part<<<gp, 256>>>(x);
    gn_comb<<<1, 32>>>();
    gn_norm<<<(ROWS_TOT * C_ / 4) / 256, 256>>>(x, gamma, beta);

    dim3 tg(8, 8, 4);
    transposeW4<<<tg, 256>>>(Wq, Wk, Wv, Wp, wt);

    // fused Q+K projection: [16384,256] @ [256,512] + [bq|bk] -> g_qk
    dim3 gQK(4, 128, 1);
    gemm_mma<true,false,false,true,false,false><<<gQK, 256, GSMEM>>>(
        xn, wtqk, bq, bk, nullptr, qk, C_, C_, 512, C_, 256, 0, 0, 0, 1.f);

    // E = exp((Q @ K^T) * C^-0.5), batched, unnormalized
    dim3 gS(32, 32, B_);
    gemm_mma<false,false,false,true,true,false><<<gS, 256, GSMEM>>>(
        qk, qk + 256, nullptr, nullptr, nullptr, attn, 512, 512, NTOK, C_, 0,
        (long)NTOK * 512, (long)NTOK * 512, (long)NTOK * NTOK, 0.0625f);

    // V projection -> vT [C][16384]
    dim3 gV(2, 128, 1);
    gemm_mma<true,false,true,true,false,false><<<gV, 256, GSMEM>>>(
        xn, wtv, bv, nullptr, nullptr, vT, C_, C_, ROWS_TOT, C_, 0, 0, 0, 0, 1.f);

    // O = (E @ V) / rowsum(E)  (row sums from register E fragments)
    dim3 gAV(2, 32, B_);
    gemm_mma<false,false,false,true,false,true><<<gAV, 256, GSMEM>>>(
        attn, vT, nullptr, nullptr, nullptr, o, NTOK, ROWS_TOT, C_, NTOK, 0,
        (long)NTOK * NTOK, (long)NTOK, (long)NTOK * C_, 1.f);

    // final projection + bias + residual -> d_out (fp32)
    gemm_mma<true,true,false,false,false,false><<<gV, 256, GSMEM>>>(
        o, wtp, bp, nullptr, xn, out, C_, C_, C_, C_, 0, 0, 0, 0, 1.f);
}

// round 9
// speedup vs baseline: 5.4366x; 1.5294x over previous
#include <cuda_runtime.h>
#include <cuda_fp16.h>
#include <cstdint>
#include <math.h>

// Problem constants: B=4, H=W=64 -> N=4096 tokens, C=256, GROUPS=8
#define B_ 4
#define NTOK 4096
#define C_ 256
#define GRP 8
#define CG 32
#define ROWS_TOT (B_*NTOK)   // 16384

// ---------------- scratch (device globals) ------------------------------------
__device__ float2 g_part[32*8];           // groupnorm partial (sum, sumsq)
__device__ float  g_xn[ROWS_TOT*C_];      // normalized input fp32 (residual)
__device__ __half g_xnh[ROWS_TOT*C_];     // normalized input fp16 (GEMM operand)
__device__ __half g_qk[ROWS_TOT*512];     // q (cols 0-255), k (cols 256-511)
__device__ __half g_vT[ROWS_TOT*C_];      // V transposed: [C_][ROWS_TOT]
__device__ __half g_o[ROWS_TOT*C_];       // attn output (pre-projection)
__device__ __half g_wt[4*C_*C_];          // transposed weights: wtq wtk wtv wtp
__device__ __half g_attn[(size_t)B_*NTOK*NTOK];  // unnormalized exp(QK^T/16), 134 MB

// ---------------- helpers -------------------------------------------------------
__device__ __forceinline__ uint32_t smem_u32(const void* p) {
    uint32_t a;
    asm("{ .reg .u64 t; cvta.to.shared.u64 t, %1; cvt.u32.u64 %0, t; }" : "=r"(a) : "l"(p));
    return a;
}
__device__ __forceinline__ void cp16(uint32_t dst, const void* src) {
    asm volatile("cp.async.cg.shared.global [%0], [%1], 16;" :: "r"(dst), "l"(src));
}
__device__ __forceinline__ uint32_t lds32u(uint32_t a) {
    uint32_t v; asm volatile("ld.shared.b32 %0, [%1];" : "=r"(v) : "r"(a));
    return v;
}

// fp16 m16n8k16 MMA, fp32 accumulate. 2x the tf32 rate, same 10-bit mantissa.
__device__ __forceinline__ void mma16816(float* d, const uint32_t* a, const uint32_t* b) {
    asm volatile(
        "mma.sync.aligned.m16n8k16.row.col.f32.f16.f16.f32 "
        "{%0,%1,%2,%3}, {%4,%5,%6,%7}, {%8,%9}, {%0,%1,%2,%3};"
        : "+f"(d[0]), "+f"(d[1]), "+f"(d[2]), "+f"(d[3])
        : "r"(a[0]), "r"(a[1]), "r"(a[2]), "r"(a[3]), "r"(b[0]), "r"(b[1]));
}
__device__ __forceinline__ float h2sum(uint32_t u) {
    __half2 h = *(__half2*)&u;
    float2 f = __half22float2(h);
    return f.x + f.y;
}

// ---------------- prep: GN partial stats + weight transposes --------------------
// grid (32, 10): y<8 -> GN partial slice; y in {8,9} -> transpose tiles.
__global__ __launch_bounds__(256) void prep(
    const float* __restrict__ x,
    const float* __restrict__ W0, const float* __restrict__ W1,
    const float* __restrict__ W2, const float* __restrict__ W3)
{
    if (blockIdx.y < 8) {
        int bg = blockIdx.x, slice = blockIdx.y;
        int b = bg >> 3, g = bg & 7;
        const float* xb = x + (size_t)b * NTOK * C_ + g * CG + (size_t)slice * 512 * C_;
        float s = 0.f, ss = 0.f;
        for (int i = threadIdx.x; i < 512 * CG; i += 256) {
            int n = i >> 5, c = i & 31;
            float v = __ldg(&xb[(size_t)n * C_ + c]);
            s += v; ss += v * v;
        }
        __shared__ float sh1[256], sh2[256];
        int t = threadIdx.x;
        sh1[t] = s; sh2[t] = ss;
        __syncthreads();
        for (int o = 128; o > 0; o >>= 1) {
            if (t < o) { sh1[t] += sh1[t + o]; sh2[t] += sh2[t + o]; }
            __syncthreads();
        }
        if (t == 0) g_part[bg * 8 + slice] = make_float2(sh1[0], sh2[0]);
    } else {
        // 64 blocks x 4 tiles = 256 (32x32) transpose tiles over 4 weights
        int idx = blockIdx.x + 32 * (blockIdx.y - 8);
        __shared__ float tsm[32][33];
        int tx = threadIdx.x & 31, ty = threadIdx.x >> 5;
        for (int tt = 0; tt < 4; tt++) {
            int tile = idx * 4 + tt;
            int w = tile >> 6, rem = tile & 63;
            int c0 = (rem & 7) * 32, k0 = (rem >> 3) * 32;
            const float* W = (w == 0) ? W0 : (w == 1) ? W1 : (w == 2) ? W2 : W3;
            __half* Wt = g_wt + (size_t)w * C_ * C_;
            __syncthreads();
#pragma unroll
            for (int j = 0; j < 4; j++)
                tsm[ty + 8 * j][tx] = W[(size_t)(k0 + ty + 8 * j) * C_ + c0 + tx];
            __syncthreads();
#pragma unroll
            for (int j = 0; j < 4; j++)
                Wt[(size_t)(c0 + ty + 8 * j) * C_ + k0 + tx] = __float2half(tsm[tx][ty + 8 * j]);
        }
    }
}

// ---------------- GroupNorm apply: combine + normalize --------------------------
__global__ __launch_bounds__(256) void gn_norm(const float* __restrict__ x,
                                               const float* __restrict__ gamma,
                                               const float* __restrict__ beta) {
    __shared__ float smean[32], srstd[32];
    if (threadIdx.x < 32) {
        int bg = threadIdx.x;
        float s = 0.f, ss = 0.f;
#pragma unroll
        for (int i = 0; i < 8; i++) {
            float2 p = g_part[bg * 8 + i];
            s += p.x; ss += p.y;
        }
        float inv = 1.f / (float)(NTOK * CG);
        float m = s * inv;
        float var = ss * inv - m * m;
        smean[bg] = m;
        srstd[bg] = rsqrtf(var + 1e-3f);
    }
    __syncthreads();
    size_t i4 = (size_t)blockIdx.x * blockDim.x + threadIdx.x;
    size_t i = i4 * 4;
    int c = (int)(i & (C_ - 1));
    size_t row = i >> 8;
    int b = (int)(row >> 12);
    int bg = b * GRP + (c >> 5);
    float m = smean[bg], r = srstd[bg];
    float4 xv = ((const float4*)x)[i4];
    float4 gv = *(const float4*)(gamma + c);
    float4 bv = *(const float4*)(beta + c);
    float4 o;
    o.x = (xv.x - m) * r * gv.x + bv.x;
    o.y = (xv.y - m) * r * gv.y + bv.y;
    o.z = (xv.z - m) * r * gv.z + bv.z;
    o.w = (xv.w - m) * r * gv.w + bv.w;
    ((float4*)g_xn)[i4] = o;                 // exact residual
    __half2 h01 = __floats2half2_rn(o.x, o.y);
    __half2 h23 = __floats2half2_rn(o.z, o.w);
    uint2 hp = make_uint2(*(uint32_t*)&h01, *(uint32_t*)&h23);
    ((uint2*)g_xnh)[i4] = hp;                // GEMM operand
}

// ---------------- fp16 mma.sync TN GEMM: D = A[M,K] @ B[N,K]^T ------------------
// 128x128 CTA tile, 8 warps of 64x32, kc=64 halves, 3-stage cp.async ring.
// 96 KB smem/CTA -> 2 CTAs/SM. EXP: D=exp(acc*scale). NORM: divide by row sums
// accumulated from the fp16 A(=E) fragments (exact softmax denominator).
#define NSTAGE 3
#define STAGE_BYTES 16384            // A tile 128x64 halves = 16 KB (B same)
#define SM_B (NSTAGE*STAGE_BYTES)
#define GSMEM (2*NSTAGE*STAGE_BYTES) // 96 KB

// swizzled smem byte offset of half (row, k) in a [128][64]-half stage
__device__ __forceinline__ uint32_t sah(int row, int k) {
    return (uint32_t)(row * 128 + ((((k >> 3) ^ (row & 7)) << 4) | ((k & 7) * 2)));
}

template<bool BIAS, bool RES, bool TRANS, bool EXP, bool NORM, bool OUTF32>
__global__ __launch_bounds__(256, 2) void gemm_h(
    const __half* __restrict__ A, const __half* __restrict__ B,
    const float* __restrict__ bias, const float* __restrict__ bias2,
    const float* __restrict__ res,
    void* __restrict__ Cv, int lda, int ldb, int ldc, int K, int bias_split,
    long sA, long sB, long sC, float scale)
{
    extern __shared__ char smem[];
    const uint32_t sb = smem_u32(smem);
    const int tid = threadIdx.x, wid = tid >> 5, lane = tid & 31;
    const int gid = lane >> 2, tig = lane & 3;
    const int row0 = blockIdx.y * 128, col0 = blockIdx.x * 128;
    const int wm = (wid & 1) * 64, wn = (wid >> 1) * 32;
    const __half* Ab = A + (size_t)blockIdx.z * sA;
    const __half* Bb = B + (size_t)blockIdx.z * sB;

    float acc[4][4][4];
#pragma unroll
    for (int i = 0; i < 4; i++)
#pragma unroll
        for (int j = 0; j < 4; j++)
#pragma unroll
            for (int e = 0; e < 4; e++) acc[i][j][e] = 0.f;

    float rowpart[4][2];
    if (NORM) {
#pragma unroll
        for (int i = 0; i < 4; i++) { rowpart[i][0] = 0.f; rowpart[i][1] = 0.f; }
    }

    const int nk = K >> 6;   // 64 halves per chunk

    auto load_chunk = [&](int ck, int st) {
        uint32_t ab = sb + st * STAGE_BYTES;
        uint32_t bbs = sb + SM_B + st * STAGE_BYTES;
        int k0 = ck * 64;
#pragma unroll
        for (int j = 0; j < 4; j++) {
            int s = tid + 256 * j;          // 0..1023 granules (16B = 8 halves)
            int r = s >> 3, g = s & 7;
            uint32_t off = (uint32_t)(r * 128 + ((g ^ (r & 7)) << 4));
            cp16(ab + off, Ab + (size_t)(row0 + r) * lda + k0 + g * 8);
            cp16(bbs + off, Bb + (size_t)(col0 + r) * ldb + k0 + g * 8);
        }
    };

#pragma unroll
    for (int p = 0; p < NSTAGE - 1; p++) {
        if (p < nk) load_chunk(p, p);
        asm volatile("cp.async.commit_group;" ::: "memory");
    }

    int st = 0, stl = NSTAGE - 1;
    for (int i = 0; i < nk; i++) {
        asm volatile("cp.async.wait_group %0;" :: "n"(NSTAGE - 2) : "memory");
        __syncthreads();
        if (i + NSTAGE - 1 < nk) load_chunk(i + NSTAGE - 1, stl);
        asm volatile("cp.async.commit_group;" ::: "memory");

        uint32_t as = sb + st * STAGE_BYTES;
        uint32_t bs = sb + SM_B + st * STAGE_BYTES;
#pragma unroll
        for (int k16 = 0; k16 < 4; k16++) {
            const int kb = k16 * 16;
            uint32_t af[4][4], bf[4][2];
#pragma unroll
            for (int mi = 0; mi < 4; mi++) {
                int r = wm + mi * 16 + gid;
                af[mi][0] = lds32u(as + sah(r,     kb + 2 * tig));
                af[mi][1] = lds32u(as + sah(r + 8, kb + 2 * tig));
                af[mi][2] = lds32u(as + sah(r,     kb + 2 * tig + 8));
                af[mi][3] = lds32u(as + sah(r + 8, kb + 2 * tig + 8));
            }
#pragma unroll
            for (int ni = 0; ni < 4; ni++) {
                int c = wn + ni * 8 + gid;
                bf[ni][0] = lds32u(bs + sah(c, kb + 2 * tig));
                bf[ni][1] = lds32u(bs + sah(c, kb + 2 * tig + 8));
            }
#pragma unroll
            for (int mi = 0; mi < 4; mi++)
#pragma unroll
                for (int ni = 0; ni < 4; ni++)
                    mma16816(acc[mi][ni], af[mi], bf[ni]);
            if (NORM) {
#pragma unroll
                for (int mi = 0; mi < 4; mi++) {
                    rowpart[mi][0] += h2sum(af[mi][0]) + h2sum(af[mi][2]);
                    rowpart[mi][1] += h2sum(af[mi][1]) + h2sum(af[mi][3]);
                }
            }
        }
        st = (st + 1 == NSTAGE) ? 0 : st + 1;
        stl = (stl + 1 == NSTAGE) ? 0 : stl + 1;
    }

    if (NORM) {
#pragma unroll
        for (int mi = 0; mi < 4; mi++)
#pragma unroll
            for (int h = 0; h < 2; h++) {
                float s = rowpart[mi][h];
                s += __shfl_xor_sync(0xffffffffu, s, 1);
                s += __shfl_xor_sync(0xffffffffu, s, 2);
                rowpart[mi][h] = 1.f / s;
            }
    }

    // epilogue: c0,c1 at (row gid, col tig*2,+1); c2,c3 at row+8
#pragma unroll
    for (int mi = 0; mi < 4; mi++) {
#pragma unroll
        for (int ni = 0; ni < 4; ni++) {
            int r0 = row0 + wm + mi * 16 + gid;
            int c = col0 + wn + ni * 8 + tig * 2;
#pragma unroll
            for (int h = 0; h < 2; h++) {
                int r = r0 + h * 8;
                float v0 = acc[mi][ni][h * 2 + 0] * scale;
                float v1 = acc[mi][ni][h * 2 + 1] * scale;
                if (NORM) {
                    float inv = rowpart[mi][h];
                    v0 *= inv; v1 *= inv;
                }
                if (EXP) { v0 = __expf(v0); v1 = __expf(v1); }
                if (BIAS) {
                    if (bias2 && c >= bias_split) {
                        float2 bb = *(const float2*)(bias2 + (c - bias_split));
                        v0 += bb.x; v1 += bb.y;
                    } else {
                        float2 bb = *(const float2*)(bias + c);
                        v0 += bb.x; v1 += bb.y;
                    }
                }
                if (RES) {
                    float2 rr = *(const float2*)(res + (size_t)r * ldc + c);
                    v0 += rr.x; v1 += rr.y;
                }
                if (OUTF32) {
                    float* Cb = (float*)Cv + (size_t)blockIdx.z * sC;
                    *(float2*)(Cb + (size_t)r * ldc + c) = make_float2(v0, v1);
                } else {
                    __half* Cb = (__half*)Cv + (size_t)blockIdx.z * sC;
                    if (TRANS) {
                        Cb[(size_t)(c)     * ldc + r] = __float2half(v0);
                        Cb[(size_t)(c + 1) * ldc + r] = __float2half(v1);
                    } else {
                        __half2 hv = __floats2half2_rn(v0, v1);
                        *(__half2*)(Cb + (size_t)r * ldc + c) = hv;
                    }
                }
            }
        }
    }
}

// -------------------------------- launch ---------------------------------------
extern "C" void kernel_launch(void* const* d_in, const int* in_sizes, int n_in,
                              void* d_out, int out_size) {
    const float* x     = (const float*)d_in[0];
    const float* gamma = (const float*)d_in[1];
    const float* beta  = (const float*)d_in[2];
    const float* Wq    = (const float*)d_in[3];
    const float* bq    = (const float*)d_in[4];
    const float* Wk    = (const float*)d_in[5];
    const float* bk    = (const float*)d_in[6];
    const float* Wv    = (const float*)d_in[7];
    const float* bv    = (const float*)d_in[8];
    const float* Wp    = (const float*)d_in[9];
    const float* bp    = (const float*)d_in[10];
    float* out = (float*)d_out;
    (void)in_sizes; (void)n_in; (void)out_size;

    float* xn;
    __half *xnh, *qk, *vT, *o, *attn, *wt;
    cudaGetSymbolAddress((void**)&xn,   g_xn);
    cudaGetSymbolAddress((void**)&xnh,  g_xnh);
    cudaGetSymbolAddress((void**)&qk,   g_qk);
    cudaGetSymbolAddress((void**)&vT,   g_vT);
    cudaGetSymbolAddress((void**)&o,    g_o);
    cudaGetSymbolAddress((void**)&attn, g_attn);
    cudaGetSymbolAddress((void**)&wt,   g_wt);
    __half* wtqk = wt;                // wtq then wtk: 512 rows of 256
    __half* wtv  = wt + 2*C_*C_;
    __half* wtp  = wt + 3*C_*C_;

    cudaFuncSetAttribute(gemm_h<true,false,false,false,false,false>, cudaFuncAttributeMaxDynamicSharedMemorySize, GSMEM);
    cudaFuncSetAttribute(gemm_h<false,false,false,true,false,false>, cudaFuncAttributeMaxDynamicSharedMemorySize, GSMEM);
    cudaFuncSetAttribute(gemm_h<true,false,true,false,false,false>,  cudaFuncAttributeMaxDynamicSharedMemorySize, GSMEM);
    cudaFuncSetAttribute(gemm_h<false,false,false,false,true,false>, cudaFuncAttributeMaxDynamicSharedMemorySize, GSMEM);
    cudaFuncSetAttribute(gemm_h<true,true,false,false,false,true>,   cudaFuncAttributeMaxDynamicSharedMemorySize, GSMEM);

    // launch idx: 0 prep, 1 gn_norm, 2 qkProj, 3 QKT, 4 vProj, 5 PV, 6 outProj
    dim3 gp(32, 10);
    prep<<<gp, 256>>>(x, Wq, Wk, Wv, Wp);
    gn_norm<<<(ROWS_TOT * C_ / 4) / 256, 256>>>(x, gamma, beta);

    // fused Q+K projection: [16384,256] @ [256,512] + [bq|bk] -> g_qk (fp16)
    dim3 gQK(4, 128, 1);
    gemm_h<true,false,false,false,false,false><<<gQK, 256, GSMEM>>>(
        xnh, wtqk, bq, bk, nullptr, qk, C_, C_, 512, C_, 256, 0, 0, 0, 1.f);

    // E = exp((Q @ K^T) / 16), batched, unnormalized, fp16
    dim3 gS(32, 32, B_);
    gemm_h<false,false,false,true,false,false><<<gS, 256, GSMEM>>>(
        qk, qk + 256, nullptr, nullptr, nullptr, attn, 512, 512, NTOK, C_, 0,
        (long)NTOK * 512, (long)NTOK * 512, (long)NTOK * NTOK, 0.0625f);

    // V projection -> vT [C][16384] (fp16, transposed store)
    dim3 gV(2, 128, 1);
    gemm_h<true,false,true,false,false,false><<<gV, 256, GSMEM>>>(
        xnh, wtv, bv, nullptr, nullptr, vT, C_, C_, ROWS_TOT, C_, 0, 0, 0, 0, 1.f);

    // O = (E @ V) / rowsum(E)  (row sums from fp16 E fragments) -> fp16
    dim3 gAV(2, 32, B_);
    gemm_h<false,false,false,false,true,false><<<gAV, 256, GSMEM>>>(
        attn, vT, nullptr, nullptr, nullptr, o, NTOK, ROWS_TOT, C_, NTOK, 0,
        (long)NTOK * NTOK, (long)NTOK, (long)NTOK * C_, 1.f);

    // final projection + bias + fp32 residual -> d_out (fp32)
    gemm_h<true,true,false,false,false,true><<<gV, 256, GSMEM>>>(
        o, wtp, bp, nullptr, xn, out, C_, C_, C_, C_, 0, 0, 0, 0, 1.f);
}

// round 12
// speedup vs baseline: 5.9177x; 1.0885x over previous
#include <cuda_runtime.h>
#include <cuda_fp16.h>
#include <cstdint>
#include <math.h>

// Problem constants: B=4, H=W=64 -> N=4096 tokens, C=256, GROUPS=8
#define B_ 4
#define NTOK 4096
#define C_ 256
#define GRP 8
#define CG 32
#define ROWS_TOT (B_*NTOK)   // 16384

// ---------------- scratch (device globals) ------------------------------------
__device__ float2 g_part[32*8];           // groupnorm partial (sum, sumsq)
__device__ float  g_xn[ROWS_TOT*C_];      // normalized input fp32 (residual)
__device__ __half g_xnh[ROWS_TOT*C_];     // normalized input fp16 (GEMM operand)
__device__ __half g_qk[ROWS_TOT*512];     // q (cols 0-255), k (cols 256-511)
__device__ __half g_vT[ROWS_TOT*C_];      // V transposed: [C_][ROWS_TOT]
__device__ __half g_o[ROWS_TOT*C_];       // attn output (pre-projection)
__device__ __half g_wt[4*C_*C_];          // transposed weights: wtq wtk wtv wtp
__device__ __half g_attn[(size_t)B_*NTOK*NTOK];  // unnormalized exp(QK^T/16), 134 MB

// ---------------- helpers -------------------------------------------------------
__device__ __forceinline__ uint32_t smem_u32(const void* p) {
    uint32_t a;
    asm("{ .reg .u64 t; cvta.to.shared.u64 t, %1; cvt.u32.u64 %0, t; }" : "=r"(a) : "l"(p));
    return a;
}
__device__ __forceinline__ void cp16(uint32_t dst, const void* src) {
    asm volatile("cp.async.cg.shared.global [%0], [%1], 16;" :: "r"(dst), "l"(src));
}
__device__ __forceinline__ void ldsm4(uint32_t& r0, uint32_t& r1, uint32_t& r2,
                                      uint32_t& r3, uint32_t addr) {
    asm volatile("ldmatrix.sync.aligned.m8n8.x4.shared.b16 {%0,%1,%2,%3}, [%4];"
                 : "=r"(r0), "=r"(r1), "=r"(r2), "=r"(r3) : "r"(addr));
}

// fp16 m16n8k16 MMA, fp32 accumulate. 2x the tf32 rate, same 10-bit mantissa.
__device__ __forceinline__ void mma16816(float* d, const uint32_t* a, const uint32_t* b) {
    asm volatile(
        "mma.sync.aligned.m16n8k16.row.col.f32.f16.f16.f32 "
        "{%0,%1,%2,%3}, {%4,%5,%6,%7}, {%8,%9}, {%0,%1,%2,%3};"
        : "+f"(d[0]), "+f"(d[1]), "+f"(d[2]), "+f"(d[3])
        : "r"(a[0]), "r"(a[1]), "r"(a[2]), "r"(a[3]), "r"(b[0]), "r"(b[1]));
}
__device__ __forceinline__ float h2sum(uint32_t u) {
    __half2 h = *(__half2*)&u;
    float2 f = __half22float2(h);
    return f.x + f.y;
}

// ---------------- prep: GN partial stats + weight transposes --------------------
// grid (32, 10): y<8 -> GN partial slice; y in {8,9} -> transpose tiles.
__global__ __launch_bounds__(256) void prep(
    const float* __restrict__ x,
    const float* __restrict__ W0, const float* __restrict__ W1,
    const float* __restrict__ W2, const float* __restrict__ W3)
{
    if (blockIdx.y < 8) {
        int bg = blockIdx.x, slice = blockIdx.y;
        int b = bg >> 3, g = bg & 7;
        const float* xb = x + (size_t)b * NTOK * C_ + g * CG + (size_t)slice * 512 * C_;
        float s = 0.f, ss = 0.f;
        for (int i = threadIdx.x; i < 512 * CG; i += 256) {
            int n = i >> 5, c = i & 31;
            float v = __ldg(&xb[(size_t)n * C_ + c]);
            s += v; ss += v * v;
        }
        __shared__ float sh1[256], sh2[256];
        int t = threadIdx.x;
        sh1[t] = s; sh2[t] = ss;
        __syncthreads();
        for (int o = 128; o > 0; o >>= 1) {
            if (t < o) { sh1[t] += sh1[t + o]; sh2[t] += sh2[t + o]; }
            __syncthreads();
        }
        if (t == 0) g_part[bg * 8 + slice] = make_float2(sh1[0], sh2[0]);
    } else {
        int idx = blockIdx.x + 32 * (blockIdx.y - 8);
        __shared__ float tsm[32][33];
        int tx = threadIdx.x & 31, ty = threadIdx.x >> 5;
        for (int tt = 0; tt < 4; tt++) {
            int tile = idx * 4 + tt;
            int w = tile >> 6, rem = tile & 63;
            int c0 = (rem & 7) * 32, k0 = (rem >> 3) * 32;
            const float* W = (w == 0) ? W0 : (w == 1) ? W1 : (w == 2) ? W2 : W3;
            __half* Wt = g_wt + (size_t)w * C_ * C_;
            __syncthreads();
#pragma unroll
            for (int j = 0; j < 4; j++)
                tsm[ty + 8 * j][tx] = W[(size_t)(k0 + ty + 8 * j) * C_ + c0 + tx];
            __syncthreads();
#pragma unroll
            for (int j = 0; j < 4; j++)
                Wt[(size_t)(c0 + ty + 8 * j) * C_ + k0 + tx] = __float2half(tsm[tx][ty + 8 * j]);
        }
    }
}

// ---------------- GroupNorm apply: combine + normalize --------------------------
__global__ __launch_bounds__(256) void gn_norm(const float* __restrict__ x,
                                               const float* __restrict__ gamma,
                                               const float* __restrict__ beta) {
    __shared__ float smean[32], srstd[32];
    if (threadIdx.x < 32) {
        int bg = threadIdx.x;
        float s = 0.f, ss = 0.f;
#pragma unroll
        for (int i = 0; i < 8; i++) {
            float2 p = g_part[bg * 8 + i];
            s += p.x; ss += p.y;
        }
        float inv = 1.f / (float)(NTOK * CG);
        float m = s * inv;
        float var = ss * inv - m * m;
        smean[bg] = m;
        srstd[bg] = rsqrtf(var + 1e-3f);
    }
    __syncthreads();
    size_t i4 = (size_t)blockIdx.x * blockDim.x + threadIdx.x;
    size_t i = i4 * 4;
    int c = (int)(i & (C_ - 1));
    size_t row = i >> 8;
    int b = (int)(row >> 12);
    int bg = b * GRP + (c >> 5);
    float m = smean[bg], r = srstd[bg];
    float4 xv = ((const float4*)x)[i4];
    float4 gv = *(const float4*)(gamma + c);
    float4 bv = *(const float4*)(beta + c);
    float4 o;
    o.x = (xv.x - m) * r * gv.x + bv.x;
    o.y = (xv.y - m) * r * gv.y + bv.y;
    o.z = (xv.z - m) * r * gv.z + bv.z;
    o.w = (xv.w - m) * r * gv.w + bv.w;
    ((float4*)g_xn)[i4] = o;                 // exact residual
    __half2 h01 = __floats2half2_rn(o.x, o.y);
    __half2 h23 = __floats2half2_rn(o.z, o.w);
    uint2 hp = make_uint2(*(uint32_t*)&h01, *(uint32_t*)&h23);
    ((uint2*)g_xnh)[i4] = hp;                // GEMM operand
}

// ---------------- fp16 mma.sync TN GEMM: D = A[M,K] @ B[N,K]^T ------------------
// 128x128 CTA tile, 8 warps of 64x32, kc=64 halves, 3-stage cp.async ring,
// ldmatrix fragment loads. 96 KB smem -> 2 CTAs/SM.
#define NSTAGE 3
#define STAGE_BYTES 16384            // 128x64 halves = 16 KB per operand stage
#define SM_B (NSTAGE*STAGE_BYTES)
#define GSMEM (2*NSTAGE*STAGE_BYTES) // 96 KB

template<bool BIAS, bool RES, bool TRANS, bool EXP, bool NORM, bool OUTF32>
__global__ __launch_bounds__(256, 2) void gemm_h(
    const __half* __restrict__ A, const __half* __restrict__ B,
    const float* __restrict__ bias, const float* __restrict__ bias2,
    const float* __restrict__ res,
    void* __restrict__ Cv, int lda, int ldb, int ldc, int K, int bias_split,
    long sA, long sB, long sC, float scale)
{
    extern __shared__ char smem[];
    const uint32_t sb = smem_u32(smem);
    const int tid = threadIdx.x, wid = tid >> 5, lane = tid & 31;
    const int gid = lane >> 2, tig = lane & 3;
    const int row0 = blockIdx.y * 128, col0 = blockIdx.x * 128;
    const int wm = (wid & 1) * 64, wn = (wid >> 1) * 32;
    const __half* Ab = A + (size_t)blockIdx.z * sA;
    const __half* Bb = B + (size_t)blockIdx.z * sB;

    float acc[4][4][4];
#pragma unroll
    for (int i = 0; i < 4; i++)
#pragma unroll
        for (int j = 0; j < 4; j++)
#pragma unroll
            for (int e = 0; e < 4; e++) acc[i][j][e] = 0.f;

    float rowpart[4][2];
    if (NORM) {
#pragma unroll
        for (int i = 0; i < 4; i++) { rowpart[i][0] = 0.f; rowpart[i][1] = 0.f; }
    }

    const int nk = K >> 6;   // 64 halves per chunk

    // ldmatrix per-lane base geometry (within a stage)
    const int amr = wm + (lane & 15);          // A matrix row (mi adds 16)
    const int ahv = lane >> 4;                 // 0: k lo 8, 1: k hi 8
    const int ar7 = amr & 7;
    const int bnr = wn + (lane & 7) + ((lane >> 4) << 3);  // B n-row (ni pair adds 16)
    const int bhv = (lane >> 3) & 1;           // 0: k lo 8, 1: k hi 8
    const int br7 = bnr & 7;

    auto load_chunk = [&](int ck, int st) {
        uint32_t ab = sb + st * STAGE_BYTES;
        uint32_t bbs = sb + SM_B + st * STAGE_BYTES;
        int k0 = ck * 64;
#pragma unroll
        for (int j = 0; j < 4; j++) {
            int s = tid + 256 * j;          // 0..1023 granules (16B = 8 halves)
            int r = s >> 3, g = s & 7;
            uint32_t off = (uint32_t)(r * 128 + ((g ^ (r & 7)) << 4));
            cp16(ab + off, Ab + (size_t)(row0 + r) * lda + k0 + g * 8);
            cp16(bbs + off, Bb + (size_t)(col0 + r) * ldb + k0 + g * 8);
        }
    };

#pragma unroll
    for (int p = 0; p < NSTAGE - 1; p++) {
        if (p < nk) load_chunk(p, p);
        asm volatile("cp.async.commit_group;" ::: "memory");
    }

    int st = 0, stl = NSTAGE - 1;
    for (int i = 0; i < nk; i++) {
        asm volatile("cp.async.wait_group %0;" :: "n"(NSTAGE - 2) : "memory");
        __syncthreads();
        if (i + NSTAGE - 1 < nk) load_chunk(i + NSTAGE - 1, stl);
        asm volatile("cp.async.commit_group;" ::: "memory");

        uint32_t as = sb + st * STAGE_BYTES + (uint32_t)(amr * 128);
        uint32_t bs = sb + SM_B + st * STAGE_BYTES + (uint32_t)(bnr * 128);
#pragma unroll
        for (int k16 = 0; k16 < 4; k16++) {
            uint32_t af[4][4], bf[4][2];
            uint32_t aswz = (uint32_t)(((k16 * 2 + ahv) ^ ar7) << 4);
            uint32_t bswz = (uint32_t)(((k16 * 2 + bhv) ^ br7) << 4);
#pragma unroll
            for (int mi = 0; mi < 4; mi++)
                ldsm4(af[mi][0], af[mi][1], af[mi][2], af[mi][3],
                      as + aswz + mi * 2048);
            ldsm4(bf[0][0], bf[0][1], bf[1][0], bf[1][1], bs + bswz);
            ldsm4(bf[2][0], bf[2][1], bf[3][0], bf[3][1], bs + bswz + 2048);
#pragma unroll
            for (int mi = 0; mi < 4; mi++)
#pragma unroll
                for (int ni = 0; ni < 4; ni++)
                    mma16816(acc[mi][ni], af[mi], bf[ni]);
            if (NORM) {
#pragma unroll
                for (int mi = 0; mi < 4; mi++) {
                    rowpart[mi][0] += h2sum(af[mi][0]) + h2sum(af[mi][2]);
                    rowpart[mi][1] += h2sum(af[mi][1]) + h2sum(af[mi][3]);
                }
            }
        }
        st = (st + 1 == NSTAGE) ? 0 : st + 1;
        stl = (stl + 1 == NSTAGE) ? 0 : stl + 1;
    }

    if (NORM) {
#pragma unroll
        for (int mi = 0; mi < 4; mi++)
#pragma unroll
            for (int h = 0; h < 2; h++) {
                float s = rowpart[mi][h];
                s += __shfl_xor_sync(0xffffffffu, s, 1);
                s += __shfl_xor_sync(0xffffffffu, s, 2);
                rowpart[mi][h] = 1.f / s;
            }
    }

    // epilogue: c0,c1 at (row gid, col tig*2,+1); c2,c3 at row+8
#pragma unroll
    for (int mi = 0; mi < 4; mi++) {
#pragma unroll
        for (int ni = 0; ni < 4; ni++) {
            int r0 = row0 + wm + mi * 16 + gid;
            int c = col0 + wn + ni * 8 + tig * 2;
#pragma unroll
            for (int h = 0; h < 2; h++) {
                int r = r0 + h * 8;
                float v0 = acc[mi][ni][h * 2 + 0] * scale;
                float v1 = acc[mi][ni][h * 2 + 1] * scale;
                if (NORM) {
                    float inv = rowpart[mi][h];
                    v0 *= inv; v1 *= inv;
                }
                if (EXP) { v0 = __expf(v0); v1 = __expf(v1); }
                if (BIAS) {
                    if (bias2 && c >= bias_split) {
                        float2 bb = *(const float2*)(bias2 + (c - bias_split));
                        v0 += bb.x; v1 += bb.y;
                    } else {
                        float2 bb = *(const float2*)(bias + c);
                        v0 += bb.x; v1 += bb.y;
                    }
                }
                if (RES) {
                    float2 rr = *(const float2*)(res + (size_t)r * ldc + c);
                    v0 += rr.x; v1 += rr.y;
                }
                if (OUTF32) {
                    float* Cb = (float*)Cv + (size_t)blockIdx.z * sC;
                    *(float2*)(Cb + (size_t)r * ldc + c) = make_float2(v0, v1);
                } else {
                    __half* Cb = (__half*)Cv + (size_t)blockIdx.z * sC;
                    if (TRANS) {
                        Cb[(size_t)(c)     * ldc + r] = __float2half(v0);
                        Cb[(size_t)(c + 1) * ldc + r] = __float2half(v1);
                    } else {
                        __half2 hv = __floats2half2_rn(v0, v1);
                        *(__half2*)(Cb + (size_t)r * ldc + c) = hv;
                    }
                }
            }
        }
    }
}

// -------------------------------- launch ---------------------------------------
extern "C" void kernel_launch(void* const* d_in, const int* in_sizes, int n_in,
                              void* d_out, int out_size) {
    const float* x     = (const float*)d_in[0];
    const float* gamma = (const float*)d_in[1];
    const float* beta  = (const float*)d_in[2];
    const float* Wq    = (const float*)d_in[3];
    const float* bq    = (const float*)d_in[4];
    const float* Wk    = (const float*)d_in[5];
    const float* bk    = (const float*)d_in[6];
    const float* Wv    = (const float*)d_in[7];
    const float* bv    = (const float*)d_in[8];
    const float* Wp    = (const float*)d_in[9];
    const float* bp    = (const float*)d_in[10];
    float* out = (float*)d_out;
    (void)in_sizes; (void)n_in; (void)out_size;

    float* xn;
    __half *xnh, *qk, *vT, *o, *attn, *wt;
    cudaGetSymbolAddress((void**)&xn,   g_xn);
    cudaGetSymbolAddress((void**)&xnh,  g_xnh);
    cudaGetSymbolAddress((void**)&qk,   g_qk);
    cudaGetSymbolAddress((void**)&vT,   g_vT);
    cudaGetSymbolAddress((void**)&o,    g_o);
    cudaGetSymbolAddress((void**)&attn, g_attn);
    cudaGetSymbolAddress((void**)&wt,   g_wt);
    __half* wtqk = wt;                // wtq then wtk: 512 rows of 256
    __half* wtv  = wt + 2*C_*C_;
    __half* wtp  = wt + 3*C_*C_;

    cudaFuncSetAttribute(gemm_h<true,false,false,false,false,false>, cudaFuncAttributeMaxDynamicSharedMemorySize, GSMEM);
    cudaFuncSetAttribute(gemm_h<false,false,false,true,false,false>, cudaFuncAttributeMaxDynamicSharedMemorySize, GSMEM);
    cudaFuncSetAttribute(gemm_h<true,false,true,false,false,false>,  cudaFuncAttributeMaxDynamicSharedMemorySize, GSMEM);
    cudaFuncSetAttribute(gemm_h<false,false,false,false,true,false>, cudaFuncAttributeMaxDynamicSharedMemorySize, GSMEM);
    cudaFuncSetAttribute(gemm_h<true,true,false,false,false,true>,   cudaFuncAttributeMaxDynamicSharedMemorySize, GSMEM);

    // launch idx: 0 prep, 1 gn_norm, 2 qkProj, 3 QKT, 4 vProj, 5 PV, 6 outProj
    dim3 gp(32, 10);
    prep<<<gp, 256>>>(x, Wq, Wk, Wv, Wp);
    gn_norm<<<(ROWS_TOT * C_ / 4) / 256, 256>>>(x, gamma, beta);

    // fused Q+K projection: [16384,256] @ [256,512] + [bq|bk] -> g_qk (fp16)
    dim3 gQK(4, 128, 1);
    gemm_h<true,false,false,false,false,false><<<gQK, 256, GSMEM>>>(
        xnh, wtqk, bq, bk, nullptr, qk, C_, C_, 512, C_, 256, 0, 0, 0, 1.f);

    // E = exp((Q @ K^T) / 16), batched, unnormalized, fp16
    dim3 gS(32, 32, B_);
    gemm_h<false,false,false,true,false,false><<<gS, 256, GSMEM>>>(
        qk, qk + 256, nullptr, nullptr, nullptr, attn, 512, 512, NTOK, C_, 0,
        (long)NTOK * 512, (long)NTOK * 512, (long)NTOK * NTOK, 0.0625f);

    // V projection -> vT [C][16384] (fp16, transposed store)
    dim3 gV(2, 128, 1);
    gemm_h<true,false,true,false,false,false><<<gV, 256, GSMEM>>>(
        xnh, wtv, bv, nullptr, nullptr, vT, C_, C_, ROWS_TOT, C_, 0, 0, 0, 0, 1.f);

    // O = (E @ V) / rowsum(E)  (row sums from fp16 E fragments) -> fp16
    dim3 gAV(2, 32, B_);
    gemm_h<false,false,false,false,true,false><<<gAV, 256, GSMEM>>>(
        attn, vT, nullptr, nullptr, nullptr, o, NTOK, ROWS_TOT, C_, NTOK, 0,
        (long)NTOK * NTOK, (long)NTOK, (long)NTOK * C_, 1.f);

    // final projection + bias + fp32 residual -> d_out (fp32)
    gemm_h<true,true,false,false,false,true><<<gV, 256, GSMEM>>>(
        o, wtp, bp, nullptr, xn, out, C_, C_, C_, C_, 0, 0, 0, 0, 1.f);
}

// round 13
// speedup vs baseline: 5.9725x; 1.0092x over previous
#include <cuda_runtime.h>
#include <cuda_fp16.h>
#include <cstdint>
#include <math.h>

// Problem constants: B=4, H=W=64 -> N=4096 tokens, C=256, GROUPS=8
#define B_ 4
#define NTOK 4096
#define C_ 256
#define GRP 8
#define CG 32
#define ROWS_TOT (B_*NTOK)   // 16384

// ---------------- scratch (device globals) ------------------------------------
__device__ float2 g_part[32*8];           // groupnorm partial (sum, sumsq)
__device__ float  g_xn[ROWS_TOT*C_];      // normalized input fp32 (residual)
__device__ __half g_xnh[ROWS_TOT*C_];     // normalized input fp16 (GEMM operand)
__device__ __half g_qk[ROWS_TOT*512];     // q (cols 0-255), k (cols 256-511)
__device__ __half g_vT[ROWS_TOT*C_];      // V transposed: [C_][ROWS_TOT]
__device__ __half g_o[ROWS_TOT*C_];       // attn output (pre-projection)
__device__ __half g_wt[4*C_*C_];          // transposed weights: wtq wtk wtv wtp
__device__ __half g_attn[(size_t)B_*NTOK*NTOK];  // unnormalized exp(QK^T/16), 134 MB

// ---------------- helpers -------------------------------------------------------
__device__ __forceinline__ uint32_t smem_u32(const void* p) {
    uint32_t a;
    asm("{ .reg .u64 t; cvta.to.shared.u64 t, %1; cvt.u32.u64 %0, t; }" : "=r"(a) : "l"(p));
    return a;
}
__device__ __forceinline__ void cp16(uint32_t dst, const void* src) {
    asm volatile("cp.async.cg.shared.global [%0], [%1], 16;" :: "r"(dst), "l"(src));
}
__device__ __forceinline__ void ldsm4(uint32_t& r0, uint32_t& r1, uint32_t& r2,
                                      uint32_t& r3, uint32_t addr) {
    asm volatile("ldmatrix.sync.aligned.m8n8.x4.shared.b16 {%0,%1,%2,%3}, [%4];"
                 : "=r"(r0), "=r"(r1), "=r"(r2), "=r"(r3) : "r"(addr));
}

// fp16 m16n8k16 MMA, fp32 accumulate.
__device__ __forceinline__ void mma16816(float* d, const uint32_t* a, const uint32_t* b) {
    asm volatile(
        "mma.sync.aligned.m16n8k16.row.col.f32.f16.f16.f32 "
        "{%0,%1,%2,%3}, {%4,%5,%6,%7}, {%8,%9}, {%0,%1,%2,%3};"
        : "+f"(d[0]), "+f"(d[1]), "+f"(d[2]), "+f"(d[3])
        : "r"(a[0]), "r"(a[1]), "r"(a[2]), "r"(a[3]), "r"(b[0]), "r"(b[1]));
}
__device__ __forceinline__ float h2sum(uint32_t u) {
    __half2 h = *(__half2*)&u;
    float2 f = __half22float2(h);
    return f.x + f.y;
}

// ---------------- prep: GN partial stats + weight transposes --------------------
__global__ __launch_bounds__(256) void prep(
    const float* __restrict__ x,
    const float* __restrict__ W0, const float* __restrict__ W1,
    const float* __restrict__ W2, const float* __restrict__ W3)
{
    if (blockIdx.y < 8) {
        int bg = blockIdx.x, slice = blockIdx.y;
        int b = bg >> 3, g = bg & 7;
        const float* xb = x + (size_t)b * NTOK * C_ + g * CG + (size_t)slice * 512 * C_;
        float s = 0.f, ss = 0.f;
        for (int i = threadIdx.x; i < 512 * CG; i += 256) {
            int n = i >> 5, c = i & 31;
            float v = __ldg(&xb[(size_t)n * C_ + c]);
            s += v; ss += v * v;
        }
        __shared__ float sh1[256], sh2[256];
        int t = threadIdx.x;
        sh1[t] = s; sh2[t] = ss;
        __syncthreads();
        for (int o = 128; o > 0; o >>= 1) {
            if (t < o) { sh1[t] += sh1[t + o]; sh2[t] += sh2[t + o]; }
            __syncthreads();
        }
        if (t == 0) g_part[bg * 8 + slice] = make_float2(sh1[0], sh2[0]);
    } else {
        int idx = blockIdx.x + 32 * (blockIdx.y - 8);
        __shared__ float tsm[32][33];
        int tx = threadIdx.x & 31, ty = threadIdx.x >> 5;
        for (int tt = 0; tt < 4; tt++) {
            int tile = idx * 4 + tt;
            int w = tile >> 6, rem = tile & 63;
            int c0 = (rem & 7) * 32, k0 = (rem >> 3) * 32;
            const float* W = (w == 0) ? W0 : (w == 1) ? W1 : (w == 2) ? W2 : W3;
            __half* Wt = g_wt + (size_t)w * C_ * C_;
            __syncthreads();
#pragma unroll
            for (int j = 0; j < 4; j++)
                tsm[ty + 8 * j][tx] = W[(size_t)(k0 + ty + 8 * j) * C_ + c0 + tx];
            __syncthreads();
#pragma unroll
            for (int j = 0; j < 4; j++)
                Wt[(size_t)(c0 + ty + 8 * j) * C_ + k0 + tx] = __float2half(tsm[tx][ty + 8 * j]);
        }
    }
}

// ---------------- GroupNorm apply: combine + normalize --------------------------
__global__ __launch_bounds__(256) void gn_norm(const float* __restrict__ x,
                                               const float* __restrict__ gamma,
                                               const float* __restrict__ beta) {
    __shared__ float smean[32], srstd[32];
    if (threadIdx.x < 32) {
        int bg = threadIdx.x;
        float s = 0.f, ss = 0.f;
#pragma unroll
        for (int i = 0; i < 8; i++) {
            float2 p = g_part[bg * 8 + i];
            s += p.x; ss += p.y;
        }
        float inv = 1.f / (float)(NTOK * CG);
        float m = s * inv;
        float var = ss * inv - m * m;
        smean[bg] = m;
        srstd[bg] = rsqrtf(var + 1e-3f);
    }
    __syncthreads();
    size_t i4 = (size_t)blockIdx.x * blockDim.x + threadIdx.x;
    size_t i = i4 * 4;
    int c = (int)(i & (C_ - 1));
    size_t row = i >> 8;
    int b = (int)(row >> 12);
    int bg = b * GRP + (c >> 5);
    float m = smean[bg], r = srstd[bg];
    float4 xv = ((const float4*)x)[i4];
    float4 gv = *(const float4*)(gamma + c);
    float4 bv = *(const float4*)(beta + c);
    float4 o;
    o.x = (xv.x - m) * r * gv.x + bv.x;
    o.y = (xv.y - m) * r * gv.y + bv.y;
    o.z = (xv.z - m) * r * gv.z + bv.z;
    o.w = (xv.w - m) * r * gv.w + bv.w;
    ((float4*)g_xn)[i4] = o;                 // exact residual
    __half2 h01 = __floats2half2_rn(o.x, o.y);
    __half2 h23 = __floats2half2_rn(o.z, o.w);
    uint2 hp = make_uint2(*(uint32_t*)&h01, *(uint32_t*)&h23);
    ((uint2*)g_xnh)[i4] = hp;                // GEMM operand
}

// ---------------- fp16 mma.sync TN GEMM: D = A[M,K] @ B[N,K]^T ------------------
// 128(M)x256(N) CTA tile, 8 warps of 64x64, kc=64 halves, 4-stage cp.async ring,
// ldmatrix fragment loads. 192 KB smem, 1 CTA/SM; 32 indep acc chains/warp.
#define NSTAGE 4
#define A_STAGE 16384                 // 128x64 halves
#define B_STAGE 32768                 // 256x64 halves
#define SM_B (NSTAGE*A_STAGE)
#define GSMEM (NSTAGE*(A_STAGE+B_STAGE))   // 192 KB

template<bool BIAS, bool RES, bool TRANS, bool EXP, bool NORM, bool OUTF32>
__global__ __launch_bounds__(256, 1) void gemm_h(
    const __half* __restrict__ A, const __half* __restrict__ B,
    const float* __restrict__ bias, const float* __restrict__ bias2,
    const float* __restrict__ res,
    void* __restrict__ Cv, int lda, int ldb, int ldc, int K, int bias_split,
    long sA, long sB, long sC, float scale)
{
    extern __shared__ char smem[];
    const uint32_t sb = smem_u32(smem);
    const int tid = threadIdx.x, wid = tid >> 5, lane = tid & 31;
    const int gid = lane >> 2, tig = lane & 3;
    const int row0 = blockIdx.y * 128, col0 = blockIdx.x * 256;
    const int wm = (wid & 1) * 64, wn = (wid >> 1) * 64;
    const __half* Ab = A + (size_t)blockIdx.z * sA;
    const __half* Bb = B + (size_t)blockIdx.z * sB;

    float acc[4][8][4];
#pragma unroll
    for (int i = 0; i < 4; i++)
#pragma unroll
        for (int j = 0; j < 8; j++)
#pragma unroll
            for (int e = 0; e < 4; e++) acc[i][j][e] = 0.f;

    float rowpart[4][2];
    if (NORM) {
#pragma unroll
        for (int i = 0; i < 4; i++) { rowpart[i][0] = 0.f; rowpart[i][1] = 0.f; }
    }

    const int nk = K >> 6;   // 64 halves per chunk

    // ldmatrix per-lane base geometry (within a stage)
    const int amr = wm + (lane & 15);          // A row (mi adds 16)
    const int ahv = lane >> 4;                 // k half select
    const int ar7 = amr & 7;
    const int bnr = wn + (lane & 7) + ((lane >> 4) << 3);  // B n-row (ni pair adds 16)
    const int bhv = (lane >> 3) & 1;
    const int br7 = bnr & 7;

    auto load_chunk = [&](int ck, int st) {
        uint32_t ab = sb + st * A_STAGE;
        uint32_t bbs = sb + SM_B + st * B_STAGE;
        int k0 = ck * 64;
#pragma unroll
        for (int j = 0; j < 4; j++) {           // A: 1024 granules
            int s = tid + 256 * j;
            int r = s >> 3, g = s & 7;
            uint32_t off = (uint32_t)(r * 128 + ((g ^ (r & 7)) << 4));
            cp16(ab + off, Ab + (size_t)(row0 + r) * lda + k0 + g * 8);
        }
#pragma unroll
        for (int j = 0; j < 8; j++) {           // B: 2048 granules
            int s = tid + 256 * j;
            int r = s >> 3, g = s & 7;
            uint32_t off = (uint32_t)(r * 128 + ((g ^ (r & 7)) << 4));
            cp16(bbs + off, Bb + (size_t)(col0 + r) * ldb + k0 + g * 8);
        }
    };

#pragma unroll
    for (int p = 0; p < NSTAGE - 1; p++) {
        if (p < nk) load_chunk(p, p);
        asm volatile("cp.async.commit_group;" ::: "memory");
    }

    int st = 0, stl = NSTAGE - 1;
    for (int i = 0; i < nk; i++) {
        asm volatile("cp.async.wait_group %0;" :: "n"(NSTAGE - 2) : "memory");
        __syncthreads();
        if (i + NSTAGE - 1 < nk) load_chunk(i + NSTAGE - 1, stl);
        asm volatile("cp.async.commit_group;" ::: "memory");

        uint32_t as = sb + st * A_STAGE + (uint32_t)(amr * 128);
        uint32_t bs = sb + SM_B + st * B_STAGE + (uint32_t)(bnr * 128);
#pragma unroll
        for (int k16 = 0; k16 < 4; k16++) {
            uint32_t af[4][4], bf[8][2];
            uint32_t aswz = (uint32_t)(((k16 * 2 + ahv) ^ ar7) << 4);
            uint32_t bswz = (uint32_t)(((k16 * 2 + bhv) ^ br7) << 4);
#pragma unroll
            for (int mi = 0; mi < 4; mi++)
                ldsm4(af[mi][0], af[mi][1], af[mi][2], af[mi][3],
                      as + aswz + mi * 2048);
#pragma unroll
            for (int np = 0; np < 4; np++)
                ldsm4(bf[2*np][0], bf[2*np][1], bf[2*np+1][0], bf[2*np+1][1],
                      bs + bswz + np * 2048);
#pragma unroll
            for (int mi = 0; mi < 4; mi++)
#pragma unroll
                for (int ni = 0; ni < 8; ni++)
                    mma16816(acc[mi][ni], af[mi], bf[ni]);
            if (NORM) {
#pragma unroll
                for (int mi = 0; mi < 4; mi++) {
                    rowpart[mi][0] += h2sum(af[mi][0]) + h2sum(af[mi][2]);
                    rowpart[mi][1] += h2sum(af[mi][1]) + h2sum(af[mi][3]);
                }
            }
        }
        st = (st + 1 == NSTAGE) ? 0 : st + 1;
        stl = (stl + 1 == NSTAGE) ? 0 : stl + 1;
    }

    if (NORM) {
#pragma unroll
        for (int mi = 0; mi < 4; mi++)
#pragma unroll
            for (int h = 0; h < 2; h++) {
                float s = rowpart[mi][h];
                s += __shfl_xor_sync(0xffffffffu, s, 1);
                s += __shfl_xor_sync(0xffffffffu, s, 2);
                rowpart[mi][h] = 1.f / s;
            }
    }

    // epilogue: c0,c1 at (row gid, col tig*2,+1); c2,c3 at row+8
#pragma unroll
    for (int mi = 0; mi < 4; mi++) {
#pragma unroll
        for (int ni = 0; ni < 8; ni++) {
            int r0 = row0 + wm + mi * 16 + gid;
            int c = col0 + wn + ni * 8 + tig * 2;
#pragma unroll
            for (int h = 0; h < 2; h++) {
                int r = r0 + h * 8;
                float v0 = acc[mi][ni][h * 2 + 0] * scale;
                float v1 = acc[mi][ni][h * 2 + 1] * scale;
                if (NORM) {
                    float inv = rowpart[mi][h];
                    v0 *= inv; v1 *= inv;
                }
                if (EXP) { v0 = __expf(v0); v1 = __expf(v1); }
                if (BIAS) {
                    if (bias2 && c >= bias_split) {
                        float2 bb = *(const float2*)(bias2 + (c - bias_split));
                        v0 += bb.x; v1 += bb.y;
                    } else {
                        float2 bb = *(const float2*)(bias + c);
                        v0 += bb.x; v1 += bb.y;
                    }
                }
                if (RES) {
                    float2 rr = *(const float2*)(res + (size_t)r * ldc + c);
                    v0 += rr.x; v1 += rr.y;
                }
                if (OUTF32) {
                    float* Cb = (float*)Cv + (size_t)blockIdx.z * sC;
                    *(float2*)(Cb + (size_t)r * ldc + c) = make_float2(v0, v1);
                } else {
                    __half* Cb = (__half*)Cv + (size_t)blockIdx.z * sC;
                    if (TRANS) {
                        Cb[(size_t)(c)     * ldc + r] = __float2half(v0);
                        Cb[(size_t)(c + 1) * ldc + r] = __float2half(v1);
                    } else {
                        __half2 hv = __floats2half2_rn(v0, v1);
                        *(__half2*)(Cb + (size_t)r * ldc + c) = hv;
                    }
                }
            }
        }
    }
}

// -------------------------------- launch ---------------------------------------
extern "C" void kernel_launch(void* const* d_in, const int* in_sizes, int n_in,
                              void* d_out, int out_size) {
    const float* x     = (const float*)d_in[0];
    const float* gamma = (const float*)d_in[1];
    const float* beta  = (const float*)d_in[2];
    const float* Wq    = (const float*)d_in[3];
    const float* bq    = (const float*)d_in[4];
    const float* Wk    = (const float*)d_in[5];
    const float* bk    = (const float*)d_in[6];
    const float* Wv    = (const float*)d_in[7];
    const float* bv    = (const float*)d_in[8];
    const float* Wp    = (const float*)d_in[9];
    const float* bp    = (const float*)d_in[10];
    float* out = (float*)d_out;
    (void)in_sizes; (void)n_in; (void)out_size;

    float* xn;
    __half *xnh, *qk, *vT, *o, *attn, *wt;
    cudaGetSymbolAddress((void**)&xn,   g_xn);
    cudaGetSymbolAddress((void**)&xnh,  g_xnh);
    cudaGetSymbolAddress((void**)&qk,   g_qk);
    cudaGetSymbolAddress((void**)&vT,   g_vT);
    cudaGetSymbolAddress((void**)&o,    g_o);
    cudaGetSymbolAddress((void**)&attn, g_attn);
    cudaGetSymbolAddress((void**)&wt,   g_wt);
    __half* wtqk = wt;                // wtq then wtk: 512 rows of 256
    __half* wtv  = wt + 2*C_*C_;
    __half* wtp  = wt + 3*C_*C_;

    cudaFuncSetAttribute(gemm_h<true,false,false,false,false,false>, cudaFuncAttributeMaxDynamicSharedMemorySize, GSMEM);
    cudaFuncSetAttribute(gemm_h<false,false,false,true,false,false>, cudaFuncAttributeMaxDynamicSharedMemorySize, GSMEM);
    cudaFuncSetAttribute(gemm_h<true,false,true,false,false,false>,  cudaFuncAttributeMaxDynamicSharedMemorySize, GSMEM);
    cudaFuncSetAttribute(gemm_h<false,false,false,false,true,false>, cudaFuncAttributeMaxDynamicSharedMemorySize, GSMEM);
    cudaFuncSetAttribute(gemm_h<true,true,false,false,false,true>,   cudaFuncAttributeMaxDynamicSharedMemorySize, GSMEM);

    // launch idx: 0 prep, 1 gn_norm, 2 qkProj, 3 QKT, 4 vProj, 5 PV, 6 outProj
    dim3 gp(32, 10);
    prep<<<gp, 256>>>(x, Wq, Wk, Wv, Wp);
    gn_norm<<<(ROWS_TOT * C_ / 4) / 256, 256>>>(x, gamma, beta);

    // fused Q+K projection: [16384,256] @ [256,512] + [bq|bk] -> g_qk (fp16)
    dim3 gQK(2, 128, 1);
    gemm_h<true,false,false,false,false,false><<<gQK, 256, GSMEM>>>(
        xnh, wtqk, bq, bk, nullptr, qk, C_, C_, 512, C_, 256, 0, 0, 0, 1.f);

    // E = exp((Q @ K^T) / 16), batched, unnormalized, fp16
    dim3 gS(16, 32, B_);
    gemm_h<false,false,false,true,false,false><<<gS, 256, GSMEM>>>(
        qk, qk + 256, nullptr, nullptr, nullptr, attn, 512, 512, NTOK, C_, 0,
        (long)NTOK * 512, (long)NTOK * 512, (long)NTOK * NTOK, 0.0625f);

    // V projection -> vT [C][16384] (fp16, transposed store)
    dim3 gV(1, 128, 1);
    gemm_h<true,false,true,false,false,false><<<gV, 256, GSMEM>>>(
        xnh, wtv, bv, nullptr, nullptr, vT, C_, C_, ROWS_TOT, C_, 0, 0, 0, 0, 1.f);

    // O = (E @ V) / rowsum(E)  (row sums from fp16 E fragments) -> fp16
    dim3 gAV(1, 32, B_);
    gemm_h<false,false,false,false,true,false><<<gAV, 256, GSMEM>>>(
        attn, vT, nullptr, nullptr, nullptr, o, NTOK, ROWS_TOT, C_, NTOK, 0,
        (long)NTOK * NTOK, (long)NTOK, (long)NTOK * C_, 1.f);

    // final projection + bias + fp32 residual -> d_out (fp32)
    gemm_h<true,true,false,false,false,true><<<gV, 256, GSMEM>>>(
        o, wtp, bp, nullptr, xn, out, C_, C_, C_, C_, 0, 0, 0, 0, 1.f);
}

// round 14
// speedup vs baseline: 5.9755x; 1.0005x over previous
#include <cuda_runtime.h>
#include <cuda_fp16.h>
#include <cstdint>
#include <math.h>

// Problem constants: B=4, H=W=64 -> N=4096 tokens, C=256, GROUPS=8
#define B_ 4
#define NTOK 4096
#define C_ 256
#define GRP 8
#define CG 32
#define ROWS_TOT (B_*NTOK)   // 16384

// ---------------- scratch (device globals) ------------------------------------
__device__ float2 g_part[32*8];           // groupnorm partial (sum, sumsq)
__device__ float  g_xn[ROWS_TOT*C_];      // normalized input fp32 (residual)
__device__ __half g_xnh[ROWS_TOT*C_];     // normalized input fp16 (GEMM operand)
__device__ __half g_qk[ROWS_TOT*512];     // q (cols 0-255), k (cols 256-511)
__device__ __half g_vT[ROWS_TOT*C_];      // V transposed: [C_][ROWS_TOT]
__device__ __half g_o[ROWS_TOT*C_];       // attn output (pre-projection)
__device__ __half g_wt[4*C_*C_];          // transposed weights: wtq wtk wtv wtp
__device__ __half g_attn[(size_t)B_*NTOK*NTOK];  // unnormalized exp(QK^T/16), 134 MB

// ---------------- helpers -------------------------------------------------------
__device__ __forceinline__ uint32_t smem_u32(const void* p) {
    uint32_t a;
    asm("{ .reg .u64 t; cvta.to.shared.u64 t, %1; cvt.u32.u64 %0, t; }" : "=r"(a) : "l"(p));
    return a;
}
__device__ __forceinline__ void cp16(uint32_t dst, const void* src) {
    asm volatile("cp.async.cg.shared.global [%0], [%1], 16;" :: "r"(dst), "l"(src));
}
__device__ __forceinline__ void ldsm4(uint32_t& r0, uint32_t& r1, uint32_t& r2,
                                      uint32_t& r3, uint32_t addr) {
    asm volatile("ldmatrix.sync.aligned.m8n8.x4.shared.b16 {%0,%1,%2,%3}, [%4];"
                 : "=r"(r0), "=r"(r1), "=r"(r2), "=r"(r3) : "r"(addr));
}

// fp16 m16n8k16 MMA, fp32 accumulate.
__device__ __forceinline__ void mma16816(float* d, const uint32_t* a, const uint32_t* b) {
    asm volatile(
        "mma.sync.aligned.m16n8k16.row.col.f32.f16.f16.f32 "
        "{%0,%1,%2,%3}, {%4,%5,%6,%7}, {%8,%9}, {%0,%1,%2,%3};"
        : "+f"(d[0]), "+f"(d[1]), "+f"(d[2]), "+f"(d[3])
        : "r"(a[0]), "r"(a[1]), "r"(a[2]), "r"(a[3]), "r"(b[0]), "r"(b[1]));
}
// fp16 m16n8k16 MMA, fp16 accumulate (2x issue rate on legacy tensor path).
__device__ __forceinline__ void mma16816h(uint32_t* d, const uint32_t* a, const uint32_t* b) {
    asm volatile(
        "mma.sync.aligned.m16n8k16.row.col.f16.f16.f16.f16 "
        "{%0,%1}, {%2,%3,%4,%5}, {%6,%7}, {%0,%1};"
        : "+r"(d[0]), "+r"(d[1])
        : "r"(a[0]), "r"(a[1]), "r"(a[2]), "r"(a[3]), "r"(b[0]), "r"(b[1]));
}
__device__ __forceinline__ float h2sum(uint32_t u) {
    __half2 h = *(__half2*)&u;
    float2 f = __half22float2(h);
    return f.x + f.y;
}

// ---------------- prep: GN partial stats + weight transposes --------------------
__global__ __launch_bounds__(256) void prep(
    const float* __restrict__ x,
    const float* __restrict__ W0, const float* __restrict__ W1,
    const float* __restrict__ W2, const float* __restrict__ W3)
{
    if (blockIdx.y < 8) {
        int bg = blockIdx.x, slice = blockIdx.y;
        int b = bg >> 3, g = bg & 7;
        const float* xb = x + (size_t)b * NTOK * C_ + g * CG + (size_t)slice * 512 * C_;
        float s = 0.f, ss = 0.f;
        for (int i = threadIdx.x; i < 512 * CG; i += 256) {
            int n = i >> 5, c = i & 31;
            float v = __ldg(&xb[(size_t)n * C_ + c]);
            s += v; ss += v * v;
        }
        __shared__ float sh1[256], sh2[256];
        int t = threadIdx.x;
        sh1[t] = s; sh2[t] = ss;
        __syncthreads();
        for (int o = 128; o > 0; o >>= 1) {
            if (t < o) { sh1[t] += sh1[t + o]; sh2[t] += sh2[t + o]; }
            __syncthreads();
        }
        if (t == 0) g_part[bg * 8 + slice] = make_float2(sh1[0], sh2[0]);
    } else {
        int idx = blockIdx.x + 32 * (blockIdx.y - 8);
        __shared__ float tsm[32][33];
        int tx = threadIdx.x & 31, ty = threadIdx.x >> 5;
        for (int tt = 0; tt < 4; tt++) {
            int tile = idx * 4 + tt;
            int w = tile >> 6, rem = tile & 63;
            int c0 = (rem & 7) * 32, k0 = (rem >> 3) * 32;
            const float* W = (w == 0) ? W0 : (w == 1) ? W1 : (w == 2) ? W2 : W3;
            __half* Wt = g_wt + (size_t)w * C_ * C_;
            __syncthreads();
#pragma unroll
            for (int j = 0; j < 4; j++)
                tsm[ty + 8 * j][tx] = W[(size_t)(k0 + ty + 8 * j) * C_ + c0 + tx];
            __syncthreads();
#pragma unroll
            for (int j = 0; j < 4; j++)
                Wt[(size_t)(c0 + ty + 8 * j) * C_ + k0 + tx] = __float2half(tsm[tx][ty + 8 * j]);
        }
    }
}

// ---------------- GroupNorm apply: combine + normalize --------------------------
__global__ __launch_bounds__(256) void gn_norm(const float* __restrict__ x,
                                               const float* __restrict__ gamma,
                                               const float* __restrict__ beta) {
    __shared__ float smean[32], srstd[32];
    if (threadIdx.x < 32) {
        int bg = threadIdx.x;
        float s = 0.f, ss = 0.f;
#pragma unroll
        for (int i = 0; i < 8; i++) {
            float2 p = g_part[bg * 8 + i];
            s += p.x; ss += p.y;
        }
        float inv = 1.f / (float)(NTOK * CG);
        float m = s * inv;
        float var = ss * inv - m * m;
        smean[bg] = m;
        srstd[bg] = rsqrtf(var + 1e-3f);
    }
    __syncthreads();
    size_t i4 = (size_t)blockIdx.x * blockDim.x + threadIdx.x;
    size_t i = i4 * 4;
    int c = (int)(i & (C_ - 1));
    size_t row = i >> 8;
    int b = (int)(row >> 12);
    int bg = b * GRP + (c >> 5);
    float m = smean[bg], r = srstd[bg];
    float4 xv = ((const float4*)x)[i4];
    float4 gv = *(const float4*)(gamma + c);
    float4 bv = *(const float4*)(beta + c);
    float4 o;
    o.x = (xv.x - m) * r * gv.x + bv.x;
    o.y = (xv.y - m) * r * gv.y + bv.y;
    o.z = (xv.z - m) * r * gv.z + bv.z;
    o.w = (xv.w - m) * r * gv.w + bv.w;
    ((float4*)g_xn)[i4] = o;                 // exact residual
    __half2 h01 = __floats2half2_rn(o.x, o.y);
    __half2 h23 = __floats2half2_rn(o.z, o.w);
    uint2 hp = make_uint2(*(uint32_t*)&h01, *(uint32_t*)&h23);
    ((uint2*)g_xnh)[i4] = hp;                // GEMM operand
}

// ---------------- shared GEMM geometry ------------------------------------------
// 128(M)x256(N) CTA tile, 8 warps of 64x64, kc=64 halves, 4-stage cp.async ring.
#define NSTAGE 4
#define A_STAGE 16384                 // 128x64 halves
#define B_STAGE 32768                 // 256x64 halves
#define SM_B (NSTAGE*A_STAGE)
#define GSMEM (NSTAGE*(A_STAGE+B_STAGE))   // 192 KB

// ---------------- fp32-acc fp16 GEMM: D = A[M,K] @ B[N,K]^T ---------------------
template<bool BIAS, bool RES, bool TRANS, bool EXP, bool NORM, bool OUTF32>
__global__ __launch_bounds__(256, 1) void gemm_h(
    const __half* __restrict__ A, const __half* __restrict__ B,
    const float* __restrict__ bias, const float* __restrict__ bias2,
    const float* __restrict__ res,
    void* __restrict__ Cv, int lda, int ldb, int ldc, int K, int bias_split,
    long sA, long sB, long sC, float scale)
{
    extern __shared__ char smem[];
    const uint32_t sb = smem_u32(smem);
    const int tid = threadIdx.x, wid = tid >> 5, lane = tid & 31;
    const int gid = lane >> 2, tig = lane & 3;
    const int row0 = blockIdx.y * 128, col0 = blockIdx.x * 256;
    const int wm = (wid & 1) * 64, wn = (wid >> 1) * 64;
    const __half* Ab = A + (size_t)blockIdx.z * sA;
    const __half* Bb = B + (size_t)blockIdx.z * sB;

    float acc[4][8][4];
#pragma unroll
    for (int i = 0; i < 4; i++)
#pragma unroll
        for (int j = 0; j < 8; j++)
#pragma unroll
            for (int e = 0; e < 4; e++) acc[i][j][e] = 0.f;

    float rowpart[4][2];
    if (NORM) {
#pragma unroll
        for (int i = 0; i < 4; i++) { rowpart[i][0] = 0.f; rowpart[i][1] = 0.f; }
    }

    const int nk = K >> 6;

    const int amr = wm + (lane & 15);
    const int ahv = lane >> 4;
    const int ar7 = amr & 7;
    const int bnr = wn + (lane & 7) + ((lane >> 4) << 3);
    const int bhv = (lane >> 3) & 1;
    const int br7 = bnr & 7;

    auto load_chunk = [&](int ck, int st) {
        uint32_t ab = sb + st * A_STAGE;
        uint32_t bbs = sb + SM_B + st * B_STAGE;
        int k0 = ck * 64;
#pragma unroll
        for (int j = 0; j < 4; j++) {
            int s = tid + 256 * j;
            int r = s >> 3, g = s & 7;
            uint32_t off = (uint32_t)(r * 128 + ((g ^ (r & 7)) << 4));
            cp16(ab + off, Ab + (size_t)(row0 + r) * lda + k0 + g * 8);
        }
#pragma unroll
        for (int j = 0; j < 8; j++) {
            int s = tid + 256 * j;
            int r = s >> 3, g = s & 7;
            uint32_t off = (uint32_t)(r * 128 + ((g ^ (r & 7)) << 4));
            cp16(bbs + off, Bb + (size_t)(col0 + r) * ldb + k0 + g * 8);
        }
    };

#pragma unroll
    for (int p = 0; p < NSTAGE - 1; p++) {
        if (p < nk) load_chunk(p, p);
        asm volatile("cp.async.commit_group;" ::: "memory");
    }

    int st = 0, stl = NSTAGE - 1;
    for (int i = 0; i < nk; i++) {
        asm volatile("cp.async.wait_group %0;" :: "n"(NSTAGE - 2) : "memory");
        __syncthreads();
        if (i + NSTAGE - 1 < nk) load_chunk(i + NSTAGE - 1, stl);
        asm volatile("cp.async.commit_group;" ::: "memory");

        uint32_t as = sb + st * A_STAGE + (uint32_t)(amr * 128);
        uint32_t bs = sb + SM_B + st * B_STAGE + (uint32_t)(bnr * 128);
#pragma unroll
        for (int k16 = 0; k16 < 4; k16++) {
            uint32_t af[4][4], bf[8][2];
            uint32_t aswz = (uint32_t)(((k16 * 2 + ahv) ^ ar7) << 4);
            uint32_t bswz = (uint32_t)(((k16 * 2 + bhv) ^ br7) << 4);
#pragma unroll
            for (int mi = 0; mi < 4; mi++)
                ldsm4(af[mi][0], af[mi][1], af[mi][2], af[mi][3],
                      as + aswz + mi * 2048);
#pragma unroll
            for (int np = 0; np < 4; np++)
                ldsm4(bf[2*np][0], bf[2*np][1], bf[2*np+1][0], bf[2*np+1][1],
                      bs + bswz + np * 2048);
#pragma unroll
            for (int mi = 0; mi < 4; mi++)
#pragma unroll
                for (int ni = 0; ni < 8; ni++)
                    mma16816(acc[mi][ni], af[mi], bf[ni]);
            if (NORM) {
#pragma unroll
                for (int mi = 0; mi < 4; mi++) {
                    rowpart[mi][0] += h2sum(af[mi][0]) + h2sum(af[mi][2]);
                    rowpart[mi][1] += h2sum(af[mi][1]) + h2sum(af[mi][3]);
                }
            }
        }
        st = (st + 1 == NSTAGE) ? 0 : st + 1;
        stl = (stl + 1 == NSTAGE) ? 0 : stl + 1;
    }

    if (NORM) {
#pragma unroll
        for (int mi = 0; mi < 4; mi++)
#pragma unroll
            for (int h = 0; h < 2; h++) {
                float s = rowpart[mi][h];
                s += __shfl_xor_sync(0xffffffffu, s, 1);
                s += __shfl_xor_sync(0xffffffffu, s, 2);
                rowpart[mi][h] = 1.f / s;
            }
    }

#pragma unroll
    for (int mi = 0; mi < 4; mi++) {
#pragma unroll
        for (int ni = 0; ni < 8; ni++) {
            int r0 = row0 + wm + mi * 16 + gid;
            int c = col0 + wn + ni * 8 + tig * 2;
#pragma unroll
            for (int h = 0; h < 2; h++) {
                int r = r0 + h * 8;
                float v0 = acc[mi][ni][h * 2 + 0] * scale;
                float v1 = acc[mi][ni][h * 2 + 1] * scale;
                if (NORM) {
                    float inv = rowpart[mi][h];
                    v0 *= inv; v1 *= inv;
                }
                if (EXP) { v0 = __expf(v0); v1 = __expf(v1); }
                if (BIAS) {
                    if (bias2 && c >= bias_split) {
                        float2 bb = *(const float2*)(bias2 + (c - bias_split));
                        v0 += bb.x; v1 += bb.y;
                    } else {
                        float2 bb = *(const float2*)(bias + c);
                        v0 += bb.x; v1 += bb.y;
                    }
                }
                if (RES) {
                    float2 rr = *(const float2*)(res + (size_t)r * ldc + c);
                    v0 += rr.x; v1 += rr.y;
                }
                if (OUTF32) {
                    float* Cb = (float*)Cv + (size_t)blockIdx.z * sC;
                    *(float2*)(Cb + (size_t)r * ldc + c) = make_float2(v0, v1);
                } else {
                    __half* Cb = (__half*)Cv + (size_t)blockIdx.z * sC;
                    if (TRANS) {
                        Cb[(size_t)(c)     * ldc + r] = __float2half(v0);
                        Cb[(size_t)(c + 1) * ldc + r] = __float2half(v1);
                    } else {
                        __half2 hv = __floats2half2_rn(v0, v1);
                        *(__half2*)(Cb + (size_t)r * ldc + c) = hv;
                    }
                }
            }
        }
    }
}

// ---------------- fp16-acc QK^T kernel: E = exp((Q @ K^T) * scale) --------------
// Same tiling as gemm_h; accumulators fp16 (2x legacy HMMA issue rate).
__global__ __launch_bounds__(256, 1) void qkt_h(
    const __half* __restrict__ A, const __half* __restrict__ B,
    __half* __restrict__ Cv, int lda, int ldb, int ldc, int K,
    long sA, long sB, long sC, float scale)
{
    extern __shared__ char smem[];
    const uint32_t sb = smem_u32(smem);
    const int tid = threadIdx.x, wid = tid >> 5, lane = tid & 31;
    const int gid = lane >> 2, tig = lane & 3;
    const int row0 = blockIdx.y * 128, col0 = blockIdx.x * 256;
    const int wm = (wid & 1) * 64, wn = (wid >> 1) * 64;
    const __half* Ab = A + (size_t)blockIdx.z * sA;
    const __half* Bb = B + (size_t)blockIdx.z * sB;

    uint32_t acc[4][8][2];
#pragma unroll
    for (int i = 0; i < 4; i++)
#pragma unroll
        for (int j = 0; j < 8; j++) { acc[i][j][0] = 0u; acc[i][j][1] = 0u; }

    const int nk = K >> 6;

    const int amr = wm + (lane & 15);
    const int ahv = lane >> 4;
    const int ar7 = amr & 7;
    const int bnr = wn + (lane & 7) + ((lane >> 4) << 3);
    const int bhv = (lane >> 3) & 1;
    const int br7 = bnr & 7;

    auto load_chunk = [&](int ck, int st) {
        uint32_t ab = sb + st * A_STAGE;
        uint32_t bbs = sb + SM_B + st * B_STAGE;
        int k0 = ck * 64;
#pragma unroll
        for (int j = 0; j < 4; j++) {
            int s = tid + 256 * j;
            int r = s >> 3, g = s & 7;
            uint32_t off = (uint32_t)(r * 128 + ((g ^ (r & 7)) << 4));
            cp16(ab + off, Ab + (size_t)(row0 + r) * lda + k0 + g * 8);
        }
#pragma unroll
        for (int j = 0; j < 8; j++) {
            int s = tid + 256 * j;
            int r = s >> 3, g = s & 7;
            uint32_t off = (uint32_t)(r * 128 + ((g ^ (r & 7)) << 4));
            cp16(bbs + off, Bb + (size_t)(col0 + r) * ldb + k0 + g * 8);
        }
    };

#pragma unroll
    for (int p = 0; p < NSTAGE - 1; p++) {
        if (p < nk) load_chunk(p, p);
        asm volatile("cp.async.commit_group;" ::: "memory");
    }

    int st = 0, stl = NSTAGE - 1;
    for (int i = 0; i < nk; i++) {
        asm volatile("cp.async.wait_group %0;" :: "n"(NSTAGE - 2) : "memory");
        __syncthreads();
        if (i + NSTAGE - 1 < nk) load_chunk(i + NSTAGE - 1, stl);
        asm volatile("cp.async.commit_group;" ::: "memory");

        uint32_t as = sb + st * A_STAGE + (uint32_t)(amr * 128);
        uint32_t bs = sb + SM_B + st * B_STAGE + (uint32_t)(bnr * 128);
#pragma unroll
        for (int k16 = 0; k16 < 4; k16++) {
            uint32_t af[4][4], bf[8][2];
            uint32_t aswz = (uint32_t)(((k16 * 2 + ahv) ^ ar7) << 4);
            uint32_t bswz = (uint32_t)(((k16 * 2 + bhv) ^ br7) << 4);
#pragma unroll
            for (int mi = 0; mi < 4; mi++)
                ldsm4(af[mi][0], af[mi][1], af[mi][2], af[mi][3],
                      as + aswz + mi * 2048);
#pragma unroll
            for (int np = 0; np < 4; np++)
                ldsm4(bf[2*np][0], bf[2*np][1], bf[2*np+1][0], bf[2*np+1][1],
                      bs + bswz + np * 2048);
#pragma unroll
            for (int mi = 0; mi < 4; mi++)
#pragma unroll
                for (int ni = 0; ni < 8; ni++)
                    mma16816h(acc[mi][ni], af[mi], bf[ni]);
        }
        st = (st + 1 == NSTAGE) ? 0 : st + 1;
        stl = (stl + 1 == NSTAGE) ? 0 : stl + 1;
    }

    // epilogue: unpack fp16 pairs, scale, exp, store fp16
    __half* Cb = Cv + (size_t)blockIdx.z * sC;
#pragma unroll
    for (int mi = 0; mi < 4; mi++) {
#pragma unroll
        for (int ni = 0; ni < 8; ni++) {
            int r0 = row0 + wm + mi * 16 + gid;
            int c = col0 + wn + ni * 8 + tig * 2;
#pragma unroll
            for (int h = 0; h < 2; h++) {
                int r = r0 + h * 8;
                float2 f = __half22float2(*(__half2*)&acc[mi][ni][h]);
                float v0 = __expf(f.x * scale);
                float v1 = __expf(f.y * scale);
                __half2 hv = __floats2half2_rn(v0, v1);
                *(__half2*)(Cb + (size_t)r * ldc + c) = hv;
            }
        }
    }
}

// -------------------------------- launch ---------------------------------------
extern "C" void kernel_launch(void* const* d_in, const int* in_sizes, int n_in,
                              void* d_out, int out_size) {
    const float* x     = (const float*)d_in[0];
    const float* gamma = (const float*)d_in[1];
    const float* beta  = (const float*)d_in[2];
    const float* Wq    = (const float*)d_in[3];
    const float* bq    = (const float*)d_in[4];
    const float* Wk    = (const float*)d_in[5];
    const float* bk    = (const float*)d_in[6];
    const float* Wv    = (const float*)d_in[7];
    const float* bv    = (const float*)d_in[8];
    const float* Wp    = (const float*)d_in[9];
    const float* bp    = (const float*)d_in[10];
    float* out = (float*)d_out;
    (void)in_sizes; (void)n_in; (void)out_size;

    float* xn;
    __half *xnh, *qk, *vT, *o, *attn, *wt;
    cudaGetSymbolAddress((void**)&xn,   g_xn);
    cudaGetSymbolAddress((void**)&xnh,  g_xnh);
    cudaGetSymbolAddress((void**)&qk,   g_qk);
    cudaGetSymbolAddress((void**)&vT,   g_vT);
    cudaGetSymbolAddress((void**)&o,    g_o);
    cudaGetSymbolAddress((void**)&attn, g_attn);
    cudaGetSymbolAddress((void**)&wt,   g_wt);
    __half* wtqk = wt;                // wtq then wtk: 512 rows of 256
    __half* wtv  = wt + 2*C_*C_;
    __half* wtp  = wt + 3*C_*C_;

    cudaFuncSetAttribute(gemm_h<true,false,false,false,false,false>, cudaFuncAttributeMaxDynamicSharedMemorySize, GSMEM);
    cudaFuncSetAttribute(qkt_h,                                      cudaFuncAttributeMaxDynamicSharedMemorySize, GSMEM);
    cudaFuncSetAttribute(gemm_h<true,false,true,false,false,false>,  cudaFuncAttributeMaxDynamicSharedMemorySize, GSMEM);
    cudaFuncSetAttribute(gemm_h<false,false,false,false,true,false>, cudaFuncAttributeMaxDynamicSharedMemorySize, GSMEM);
    cudaFuncSetAttribute(gemm_h<true,true,false,false,false,true>,   cudaFuncAttributeMaxDynamicSharedMemorySize, GSMEM);

    // launch idx: 0 prep, 1 gn_norm, 2 qkProj, 3 QKT, 4 vProj, 5 PV, 6 outProj
    dim3 gp(32, 10);
    prep<<<gp, 256>>>(x, Wq, Wk, Wv, Wp);
    gn_norm<<<(ROWS_TOT * C_ / 4) / 256, 256>>>(x, gamma, beta);

    // fused Q+K projection: [16384,256] @ [256,512] + [bq|bk] -> g_qk (fp16)
    dim3 gQK(2, 128, 1);
    gemm_h<true,false,false,false,false,false><<<gQK, 256, GSMEM>>>(
        xnh, wtqk, bq, bk, nullptr, qk, C_, C_, 512, C_, 256, 0, 0, 0, 1.f);

    // E = exp((Q @ K^T) / 16), batched, unnormalized, fp16-acc HMMA
    dim3 gS(16, 32, B_);
    qkt_h<<<gS, 256, GSMEM>>>(
        qk, qk + 256, attn, 512, 512, NTOK, C_,
        (long)NTOK * 512, (long)NTOK * 512, (long)NTOK * NTOK, 0.0625f);

    // V projection -> vT [C][16384] (fp16, transposed store)
    dim3 gV(1, 128, 1);
    gemm_h<true,false,true,false,false,false><<<gV, 256, GSMEM>>>(
        xnh, wtv, bv, nullptr, nullptr, vT, C_, C_, ROWS_TOT, C_, 0, 0, 0, 0, 1.f);

    // O = (E @ V) / rowsum(E)  (row sums from fp16 E fragments; fp32 acc) -> fp16
    dim3 gAV(1, 32, B_);
    gemm_h<false,false,false,false,true,false><<<gAV, 256, GSMEM>>>(
        attn, vT, nullptr, nullptr, nullptr, o, NTOK, ROWS_TOT, C_, NTOK, 0,
        (long)NTOK * NTOK, (long)NTOK, (long)NTOK * C_, 1.f);

    // final projection + bias + fp32 residual -> d_out (fp32)
    gemm_h<true,true,false,false,false,true><<<gV, 256, GSMEM>>>(
        o, wtp, bp, nullptr, xn, out, C_, C_, C_, C_, 0, 0, 0, 0, 1.f);
}

// round 15
// speedup vs baseline: 6.0039x; 1.0048x over previous
#include <cuda_runtime.h>
#include <cuda_fp16.h>
#include <cstdint>
#include <math.h>

// Problem constants: B=4, H=W=64 -> N=4096 tokens, C=256, GROUPS=8
#define B_ 4
#define NTOK 4096
#define C_ 256
#define GRP 8
#define CG 32
#define ROWS_TOT (B_*NTOK)   // 16384

// ---------------- scratch (device globals) ------------------------------------
__device__ float2 g_part[32*8];           // groupnorm partial (sum, sumsq)
__device__ float  g_b3[768];              // packed bq|bk|bv
__device__ float  g_xn[ROWS_TOT*C_];      // normalized input fp32 (residual)
__device__ __half g_xnh[ROWS_TOT*C_];     // normalized input fp16 (GEMM operand)
__device__ __half g_qk[ROWS_TOT*512];     // q (cols 0-255), k (cols 256-511)
__device__ __half g_vT[ROWS_TOT*C_];      // V transposed: [C_][ROWS_TOT]
__device__ __half g_o[ROWS_TOT*C_];       // attn output (pre-projection)
__device__ __half g_wt[4*C_*C_];          // transposed weights: wtq wtk wtv wtp
__device__ __half g_attn[(size_t)B_*NTOK*NTOK];  // unnormalized exp(QK^T/16), 134 MB

// ---------------- helpers -------------------------------------------------------
__device__ __forceinline__ uint32_t smem_u32(const void* p) {
    uint32_t a;
    asm("{ .reg .u64 t; cvta.to.shared.u64 t, %1; cvt.u32.u64 %0, t; }" : "=r"(a) : "l"(p));
    return a;
}
__device__ __forceinline__ void cp16(uint32_t dst, const void* src) {
    asm volatile("cp.async.cg.shared.global [%0], [%1], 16;" :: "r"(dst), "l"(src));
}
__device__ __forceinline__ void ldsm4(uint32_t& r0, uint32_t& r1, uint32_t& r2,
                                      uint32_t& r3, uint32_t addr) {
    asm volatile("ldmatrix.sync.aligned.m8n8.x4.shared.b16 {%0,%1,%2,%3}, [%4];"
                 : "=r"(r0), "=r"(r1), "=r"(r2), "=r"(r3) : "r"(addr));
}

// fp16 m16n8k16 MMA, fp32 accumulate.
__device__ __forceinline__ void mma16816(float* d, const uint32_t* a, const uint32_t* b) {
    asm volatile(
        "mma.sync.aligned.m16n8k16.row.col.f32.f16.f16.f32 "
        "{%0,%1,%2,%3}, {%4,%5,%6,%7}, {%8,%9}, {%0,%1,%2,%3};"
        : "+f"(d[0]), "+f"(d[1]), "+f"(d[2]), "+f"(d[3])
        : "r"(a[0]), "r"(a[1]), "r"(a[2]), "r"(a[3]), "r"(b[0]), "r"(b[1]));
}
__device__ __forceinline__ float h2sum(uint32_t u) {
    __half2 h = *(__half2*)&u;
    float2 f = __half22float2(h);
    return f.x + f.y;
}

// ---------------- prep: GN partial stats + weight transposes + bias pack --------
__global__ __launch_bounds__(256) void prep(
    const float* __restrict__ x,
    const float* __restrict__ W0, const float* __restrict__ W1,
    const float* __restrict__ W2, const float* __restrict__ W3,
    const float* __restrict__ bq, const float* __restrict__ bk,
    const float* __restrict__ bv)
{
    if (blockIdx.y < 8) {
        int bg = blockIdx.x, slice = blockIdx.y;
        int b = bg >> 3, g = bg & 7;
        const float* xb = x + (size_t)b * NTOK * C_ + g * CG + (size_t)slice * 512 * C_;
        float s = 0.f, ss = 0.f;
        for (int i = threadIdx.x; i < 512 * CG; i += 256) {
            int n = i >> 5, c = i & 31;
            float v = __ldg(&xb[(size_t)n * C_ + c]);
            s += v; ss += v * v;
        }
        __shared__ float sh1[256], sh2[256];
        int t = threadIdx.x;
        sh1[t] = s; sh2[t] = ss;
        __syncthreads();
        for (int o = 128; o > 0; o >>= 1) {
            if (t < o) { sh1[t] += sh1[t + o]; sh2[t] += sh2[t + o]; }
            __syncthreads();
        }
        if (t == 0) g_part[bg * 8 + slice] = make_float2(sh1[0], sh2[0]);
    } else {
        int idx = blockIdx.x + 32 * (blockIdx.y - 8);
        __shared__ float tsm[32][33];
        int tx = threadIdx.x & 31, ty = threadIdx.x >> 5;
        for (int tt = 0; tt < 4; tt++) {
            int tile = idx * 4 + tt;
            int w = tile >> 6, rem = tile & 63;
            int c0 = (rem & 7) * 32, k0 = (rem >> 3) * 32;
            const float* W = (w == 0) ? W0 : (w == 1) ? W1 : (w == 2) ? W2 : W3;
            __half* Wt = g_wt + (size_t)w * C_ * C_;
            __syncthreads();
#pragma unroll
            for (int j = 0; j < 4; j++)
                tsm[ty + 8 * j][tx] = W[(size_t)(k0 + ty + 8 * j) * C_ + c0 + tx];
            __syncthreads();
#pragma unroll
            for (int j = 0; j < 4; j++)
                Wt[(size_t)(c0 + ty + 8 * j) * C_ + k0 + tx] = __float2half(tsm[tx][ty + 8 * j]);
        }
        if (blockIdx.x == 31 && blockIdx.y == 9) {
            for (int i = threadIdx.x; i < 768; i += 256) {
                float v = (i < 256) ? bq[i] : (i < 512) ? bk[i - 256] : bv[i - 512];
                g_b3[i] = v;
            }
        }
    }
}

// ---------------- GroupNorm apply: combine + normalize --------------------------
__global__ __launch_bounds__(256) void gn_norm(const float* __restrict__ x,
                                               const float* __restrict__ gamma,
                                               const float* __restrict__ beta) {
    __shared__ float smean[32], srstd[32];
    if (threadIdx.x < 32) {
        int bg = threadIdx.x;
        float s = 0.f, ss = 0.f;
#pragma unroll
        for (int i = 0; i < 8; i++) {
            float2 p = g_part[bg * 8 + i];
            s += p.x; ss += p.y;
        }
        float inv = 1.f / (float)(NTOK * CG);
        float m = s * inv;
        float var = ss * inv - m * m;
        smean[bg] = m;
        srstd[bg] = rsqrtf(var + 1e-3f);
    }
    __syncthreads();
    size_t i4 = (size_t)blockIdx.x * blockDim.x + threadIdx.x;
    size_t i = i4 * 4;
    int c = (int)(i & (C_ - 1));
    size_t row = i >> 8;
    int b = (int)(row >> 12);
    int bg = b * GRP + (c >> 5);
    float m = smean[bg], r = srstd[bg];
    float4 xv = ((const float4*)x)[i4];
    float4 gv = *(const float4*)(gamma + c);
    float4 bv = *(const float4*)(beta + c);
    float4 o;
    o.x = (xv.x - m) * r * gv.x + bv.x;
    o.y = (xv.y - m) * r * gv.y + bv.y;
    o.z = (xv.z - m) * r * gv.z + bv.z;
    o.w = (xv.w - m) * r * gv.w + bv.w;
    ((float4*)g_xn)[i4] = o;                 // exact residual
    __half2 h01 = __floats2half2_rn(o.x, o.y);
    __half2 h23 = __floats2half2_rn(o.z, o.w);
    uint2 hp = make_uint2(*(uint32_t*)&h01, *(uint32_t*)&h23);
    ((uint2*)g_xnh)[i4] = hp;                // GEMM operand
}

// ---------------- fp16 mma.sync TN GEMM: D = A[M,K] @ B[N,K]^T ------------------
// 128x128 CTA tile, 8 warps of 64x32, kc=64 halves, 3-stage cp.async ring,
// ldmatrix fragment loads. 96 KB smem -> 2 CTAs/SM.
// QKVE: merged QKV projection epilogue (cols<512 -> qk, cols>=512 -> vT).
#define NSTAGE 3
#define STAGE_BYTES 16384            // 128x64 halves
#define SM_B (NSTAGE*STAGE_BYTES)
#define GSMEM (2*NSTAGE*STAGE_BYTES) // 96 KB

template<bool BIAS, bool RES, bool EXP, bool NORM, bool OUTF32, bool QKVE>
__global__ __launch_bounds__(256, 2) void gemm_h(
    const __half* __restrict__ A, const __half* __restrict__ B,
    const float* __restrict__ bias, const float* __restrict__ res,
    __half* __restrict__ vtp,
    void* __restrict__ Cv, int lda, int ldb, int ldc, int K,
    long sA, long sB, long sC, float scale)
{
    extern __shared__ char smem[];
    const uint32_t sb = smem_u32(smem);
    const int tid = threadIdx.x, wid = tid >> 5, lane = tid & 31;
    const int gid = lane >> 2, tig = lane & 3;
    const int row0 = blockIdx.y * 128, col0 = blockIdx.x * 128;
    const int wm = (wid & 1) * 64, wn = (wid >> 1) * 32;
    const __half* Ab = A + (size_t)blockIdx.z * sA;
    const __half* Bb = B + (size_t)blockIdx.z * sB;

    float acc[4][4][4];
#pragma unroll
    for (int i = 0; i < 4; i++)
#pragma unroll
        for (int j = 0; j < 4; j++)
#pragma unroll
            for (int e = 0; e < 4; e++) acc[i][j][e] = 0.f;

    float rowpart[4][2];
    if (NORM) {
#pragma unroll
        for (int i = 0; i < 4; i++) { rowpart[i][0] = 0.f; rowpart[i][1] = 0.f; }
    }

    const int nk = K >> 6;   // 64 halves per chunk

    const int amr = wm + (lane & 15);
    const int ahv = lane >> 4;
    const int ar7 = amr & 7;
    const int bnr = wn + (lane & 7) + ((lane >> 4) << 3);
    const int bhv = (lane >> 3) & 1;
    const int br7 = bnr & 7;

    auto load_chunk = [&](int ck, int st) {
        uint32_t ab = sb + st * STAGE_BYTES;
        uint32_t bbs = sb + SM_B + st * STAGE_BYTES;
        int k0 = ck * 64;
#pragma unroll
        for (int j = 0; j < 4; j++) {
            int s = tid + 256 * j;
            int r = s >> 3, g = s & 7;
            uint32_t off = (uint32_t)(r * 128 + ((g ^ (r & 7)) << 4));
            cp16(ab + off, Ab + (size_t)(row0 + r) * lda + k0 + g * 8);
            cp16(bbs + off, Bb + (size_t)(col0 + r) * ldb + k0 + g * 8);
        }
    };

#pragma unroll
    for (int p = 0; p < NSTAGE - 1; p++) {
        if (p < nk) load_chunk(p, p);
        asm volatile("cp.async.commit_group;" ::: "memory");
    }

    int st = 0, stl = NSTAGE - 1;
    for (int i = 0; i < nk; i++) {
        asm volatile("cp.async.wait_group %0;" :: "n"(NSTAGE - 2) : "memory");
        __syncthreads();
        if (i + NSTAGE - 1 < nk) load_chunk(i + NSTAGE - 1, stl);
        asm volatile("cp.async.commit_group;" ::: "memory");

        uint32_t as = sb + st * STAGE_BYTES + (uint32_t)(amr * 128);
        uint32_t bs = sb + SM_B + st * STAGE_BYTES + (uint32_t)(bnr * 128);
#pragma unroll
        for (int k16 = 0; k16 < 4; k16++) {
            uint32_t af[4][4], bf[4][2];
            uint32_t aswz = (uint32_t)(((k16 * 2 + ahv) ^ ar7) << 4);
            uint32_t bswz = (uint32_t)(((k16 * 2 + bhv) ^ br7) << 4);
#pragma unroll
            for (int mi = 0; mi < 4; mi++)
                ldsm4(af[mi][0], af[mi][1], af[mi][2], af[mi][3],
                      as + aswz + mi * 2048);
            ldsm4(bf[0][0], bf[0][1], bf[1][0], bf[1][1], bs + bswz);
            ldsm4(bf[2][0], bf[2][1], bf[3][0], bf[3][1], bs + bswz + 2048);
#pragma unroll
            for (int mi = 0; mi < 4; mi++)
#pragma unroll
                for (int ni = 0; ni < 4; ni++)
                    mma16816(acc[mi][ni], af[mi], bf[ni]);
            if (NORM) {
#pragma unroll
                for (int mi = 0; mi < 4; mi++) {
                    rowpart[mi][0] += h2sum(af[mi][0]) + h2sum(af[mi][2]);
                    rowpart[mi][1] += h2sum(af[mi][1]) + h2sum(af[mi][3]);
                }
            }
        }
        st = (st + 1 == NSTAGE) ? 0 : st + 1;
        stl = (stl + 1 == NSTAGE) ? 0 : stl + 1;
    }

    if (NORM) {
#pragma unroll
        for (int mi = 0; mi < 4; mi++)
#pragma unroll
            for (int h = 0; h < 2; h++) {
                float s = rowpart[mi][h];
                s += __shfl_xor_sync(0xffffffffu, s, 1);
                s += __shfl_xor_sync(0xffffffffu, s, 2);
                rowpart[mi][h] = 1.f / s;
            }
    }

    // epilogue: c0,c1 at (row gid, col tig*2,+1); c2,c3 at row+8
#pragma unroll
    for (int mi = 0; mi < 4; mi++) {
#pragma unroll
        for (int ni = 0; ni < 4; ni++) {
            int r0 = row0 + wm + mi * 16 + gid;
            int c = col0 + wn + ni * 8 + tig * 2;
#pragma unroll
            for (int h = 0; h < 2; h++) {
                int r = r0 + h * 8;
                float v0 = acc[mi][ni][h * 2 + 0] * scale;
                float v1 = acc[mi][ni][h * 2 + 1] * scale;
                if (NORM) {
                    float inv = rowpart[mi][h];
                    v0 *= inv; v1 *= inv;
                }
                if (EXP) { v0 = __expf(v0); v1 = __expf(v1); }
                if (BIAS) {
                    float2 bb = *(const float2*)(bias + c);
                    v0 += bb.x; v1 += bb.y;
                }
                if (RES) {
                    float2 rr = *(const float2*)(res + (size_t)r * ldc + c);
                    v0 += rr.x; v1 += rr.y;
                }
                if (QKVE) {
                    // cols 0-511: q|k row-major (ldc=512); cols 512-767: vT
                    if (c < 512) {
                        __half* Cb = (__half*)Cv;
                        __half2 hv = __floats2half2_rn(v0, v1);
                        *(__half2*)(Cb + (size_t)r * 512 + c) = hv;
                    } else {
                        vtp[(size_t)(c - 512) * ROWS_TOT + r] = __float2half(v0);
                        vtp[(size_t)(c - 511) * ROWS_TOT + r] = __float2half(v1);
                    }
                } else if (OUTF32) {
                    float* Cb = (float*)Cv + (size_t)blockIdx.z * sC;
                    *(float2*)(Cb + (size_t)r * ldc + c) = make_float2(v0, v1);
                } else {
                    __half* Cb = (__half*)Cv + (size_t)blockIdx.z * sC;
                    __half2 hv = __floats2half2_rn(v0, v1);
                    *(__half2*)(Cb + (size_t)r * ldc + c) = hv;
                }
            }
        }
    }
}

// -------------------------------- launch ---------------------------------------
extern "C" void kernel_launch(void* const* d_in, const int* in_sizes, int n_in,
                              void* d_out, int out_size) {
    const float* x     = (const float*)d_in[0];
    const float* gamma = (const float*)d_in[1];
    const float* beta  = (const float*)d_in[2];
    const float* Wq    = (const float*)d_in[3];
    const float* bq    = (const float*)d_in[4];
    const float* Wk    = (const float*)d_in[5];
    const float* bk    = (const float*)d_in[6];
    const float* Wv    = (const float*)d_in[7];
    const float* bv    = (const float*)d_in[8];
    const float* Wp    = (const float*)d_in[9];
    const float* bp    = (const float*)d_in[10];
    float* out = (float*)d_out;
    (void)in_sizes; (void)n_in; (void)out_size;

    float *xn, *b3;
    __half *xnh, *qk, *vT, *o, *attn, *wt;
    cudaGetSymbolAddress((void**)&xn,   g_xn);
    cudaGetSymbolAddress((void**)&b3,   g_b3);
    cudaGetSymbolAddress((void**)&xnh,  g_xnh);
    cudaGetSymbolAddress((void**)&qk,   g_qk);
    cudaGetSymbolAddress((void**)&vT,   g_vT);
    cudaGetSymbolAddress((void**)&o,    g_o);
    cudaGetSymbolAddress((void**)&attn, g_attn);
    cudaGetSymbolAddress((void**)&wt,   g_wt);
    __half* wtqkv = wt;               // wtq|wtk|wtv: 768 rows of 256
    __half* wtp   = wt + 3*C_*C_;

    cudaFuncSetAttribute(gemm_h<true,false,false,false,false,true>,  cudaFuncAttributeMaxDynamicSharedMemorySize, GSMEM);
    cudaFuncSetAttribute(gemm_h<false,false,true,false,false,false>, cudaFuncAttributeMaxDynamicSharedMemorySize, GSMEM);
    cudaFuncSetAttribute(gemm_h<false,false,false,true,false,false>, cudaFuncAttributeMaxDynamicSharedMemorySize, GSMEM);
    cudaFuncSetAttribute(gemm_h<true,true,false,false,true,false>,   cudaFuncAttributeMaxDynamicSharedMemorySize, GSMEM);

    // launch idx: 0 prep, 1 gn_norm, 2 qkvProj, 3 QKT, 4 PV, 5 outProj
    dim3 gp(32, 10);
    prep<<<gp, 256>>>(x, Wq, Wk, Wv, Wp, bq, bk, bv);
    gn_norm<<<(ROWS_TOT * C_ / 4) / 256, 256>>>(x, gamma, beta);

    // merged QKV projection: [16384,256] @ [256,768] + b3 -> qk (cols<512), vT
    dim3 gQKV(6, 128, 1);
    gemm_h<true,false,false,false,false,true><<<gQKV, 256, GSMEM>>>(
        xnh, wtqkv, b3, nullptr, vT, qk, C_, C_, 512, C_, 0, 0, 0, 1.f);

    // E = exp((Q @ K^T) / 16), batched, unnormalized, fp16
    dim3 gS(32, 32, B_);
    gemm_h<false,false,true,false,false,false><<<gS, 256, GSMEM>>>(
        qk, qk + 256, nullptr, nullptr, nullptr, attn, 512, 512, NTOK, C_,
        (long)NTOK * 512, (long)NTOK * 512, (long)NTOK * NTOK, 0.0625f);

    // O = (E @ V) / rowsum(E)  (row sums from fp16 E fragments) -> fp16
    dim3 gAV(2, 32, B_);
    gemm_h<false,false,false,true,false,false><<<gAV, 256, GSMEM>>>(
        attn, vT, nullptr, nullptr, nullptr, o, NTOK, ROWS_TOT, C_, NTOK,
        (long)NTOK * NTOK, (long)NTOK, (long)NTOK * C_, 1.f);

    // final projection + bias + fp32 residual -> d_out (fp32)
    dim3 gP(2, 128, 1);
    gemm_h<true,true,false,false,true,false><<<gP, 256, GSMEM>>>(
        o, wtp, bp, xn, nullptr, out, C_, C_, C_, C_, 0, 0, 0, 1.f);
}

// round 16
// speedup vs baseline: 6.0126x; 1.0014x over previous
#include <cuda_runtime.h>
#include <cuda_fp16.h>
#include <cstdint>
#include <math.h>

// Problem constants: B=4, H=W=64 -> N=4096 tokens, C=256, GROUPS=8
#define B_ 4
#define NTOK 4096
#define C_ 256
#define GRP 8
#define CG 32
#define ROWS_TOT (B_*NTOK)   // 16384

// ---------------- scratch (device globals) ------------------------------------
__device__ float2 g_part[32*8];           // groupnorm partial (sum, sumsq)
__device__ float  g_b3[768];              // packed bq|bk|bv
__device__ __half g_xnh[ROWS_TOT*C_];     // normalized input fp16 (GEMM operand + residual)
__device__ __half g_qk[ROWS_TOT*512];     // q (cols 0-255), k (cols 256-511)
__device__ __half g_vT[ROWS_TOT*C_];      // V transposed: [C_][ROWS_TOT]
__device__ __half g_o[ROWS_TOT*C_];       // attn output (pre-projection)
__device__ __half g_wt[4*C_*C_];          // transposed weights: wtq wtk wtv wtp
__device__ __half g_attn[(size_t)B_*NTOK*NTOK];  // unnormalized exp(QK^T/16), 134 MB

// ---------------- helpers -------------------------------------------------------
__device__ __forceinline__ uint32_t smem_u32(const void* p) {
    uint32_t a;
    asm("{ .reg .u64 t; cvta.to.shared.u64 t, %1; cvt.u32.u64 %0, t; }" : "=r"(a) : "l"(p));
    return a;
}
__device__ __forceinline__ void cp16(uint32_t dst, const void* src) {
    asm volatile("cp.async.cg.shared.global [%0], [%1], 16;" :: "r"(dst), "l"(src));
}
__device__ __forceinline__ void ldsm4(uint32_t& r0, uint32_t& r1, uint32_t& r2,
                                      uint32_t& r3, uint32_t addr) {
    asm volatile("ldmatrix.sync.aligned.m8n8.x4.shared.b16 {%0,%1,%2,%3}, [%4];"
                 : "=r"(r0), "=r"(r1), "=r"(r2), "=r"(r3) : "r"(addr));
}

// fp16 m16n8k16 MMA, fp32 accumulate.
__device__ __forceinline__ void mma16816(float* d, const uint32_t* a, const uint32_t* b) {
    asm volatile(
        "mma.sync.aligned.m16n8k16.row.col.f32.f16.f16.f32 "
        "{%0,%1,%2,%3}, {%4,%5,%6,%7}, {%8,%9}, {%0,%1,%2,%3};"
        : "+f"(d[0]), "+f"(d[1]), "+f"(d[2]), "+f"(d[3])
        : "r"(a[0]), "r"(a[1]), "r"(a[2]), "r"(a[3]), "r"(b[0]), "r"(b[1]));
}
__device__ __forceinline__ float h2sum(uint32_t u) {
    __half2 h = *(__half2*)&u;
    float2 f = __half22float2(h);
    return f.x + f.y;
}

// ---------------- prep: GN partial stats + weight transposes + bias pack --------
__global__ __launch_bounds__(256) void prep(
    const float* __restrict__ x,
    const float* __restrict__ W0, const float* __restrict__ W1,
    const float* __restrict__ W2, const float* __restrict__ W3,
    const float* __restrict__ bq, const float* __restrict__ bk,
    const float* __restrict__ bv)
{
    if (blockIdx.y < 8) {
        int bg = blockIdx.x, slice = blockIdx.y;
        int b = bg >> 3, g = bg & 7;
        const float* xb = x + (size_t)b * NTOK * C_ + g * CG + (size_t)slice * 512 * C_;
        float s = 0.f, ss = 0.f;
        for (int i = threadIdx.x; i < 512 * CG; i += 256) {
            int n = i >> 5, c = i & 31;
            float v = __ldg(&xb[(size_t)n * C_ + c]);
            s += v; ss += v * v;
        }
        __shared__ float sh1[256], sh2[256];
        int t = threadIdx.x;
        sh1[t] = s; sh2[t] = ss;
        __syncthreads();
        for (int o = 128; o > 0; o >>= 1) {
            if (t < o) { sh1[t] += sh1[t + o]; sh2[t] += sh2[t + o]; }
            __syncthreads();
        }
        if (t == 0) g_part[bg * 8 + slice] = make_float2(sh1[0], sh2[0]);
    } else {
        int idx = blockIdx.x + 32 * (blockIdx.y - 8);
        __shared__ float tsm[32][33];
        int tx = threadIdx.x & 31, ty = threadIdx.x >> 5;
        for (int tt = 0; tt < 4; tt++) {
            int tile = idx * 4 + tt;
            int w = tile >> 6, rem = tile & 63;
            int c0 = (rem & 7) * 32, k0 = (rem >> 3) * 32;
            const float* W = (w == 0) ? W0 : (w == 1) ? W1 : (w == 2) ? W2 : W3;
            __half* Wt = g_wt + (size_t)w * C_ * C_;
            __syncthreads();
#pragma unroll
            for (int j = 0; j < 4; j++)
                tsm[ty + 8 * j][tx] = W[(size_t)(k0 + ty + 8 * j) * C_ + c0 + tx];
            __syncthreads();
#pragma unroll
            for (int j = 0; j < 4; j++)
                Wt[(size_t)(c0 + ty + 8 * j) * C_ + k0 + tx] = __float2half(tsm[tx][ty + 8 * j]);
        }
        if (blockIdx.x == 31 && blockIdx.y == 9) {
            for (int i = threadIdx.x; i < 768; i += 256) {
                float v = (i < 256) ? bq[i] : (i < 512) ? bk[i - 256] : bv[i - 512];
                g_b3[i] = v;
            }
        }
    }
}

// ---------------- GroupNorm apply: combine + normalize (fp16 out only) ----------
__global__ __launch_bounds__(256) void gn_norm(const float* __restrict__ x,
                                               const float* __restrict__ gamma,
                                               const float* __restrict__ beta) {
    __shared__ float smean[32], srstd[32];
    if (threadIdx.x < 32) {
        int bg = threadIdx.x;
        float s = 0.f, ss = 0.f;
#pragma unroll
        for (int i = 0; i < 8; i++) {
            float2 p = g_part[bg * 8 + i];
            s += p.x; ss += p.y;
        }
        float inv = 1.f / (float)(NTOK * CG);
        float m = s * inv;
        float var = ss * inv - m * m;
        smean[bg] = m;
        srstd[bg] = rsqrtf(var + 1e-3f);
    }
    __syncthreads();
    size_t i4 = (size_t)blockIdx.x * blockDim.x + threadIdx.x;
    size_t i = i4 * 4;
    int c = (int)(i & (C_ - 1));
    size_t row = i >> 8;
    int b = (int)(row >> 12);
    int bg = b * GRP + (c >> 5);
    float m = smean[bg], r = srstd[bg];
    float4 xv = ((const float4*)x)[i4];
    float4 gv = *(const float4*)(gamma + c);
    float4 bv = *(const float4*)(beta + c);
    float4 o;
    o.x = (xv.x - m) * r * gv.x + bv.x;
    o.y = (xv.y - m) * r * gv.y + bv.y;
    o.z = (xv.z - m) * r * gv.z + bv.z;
    o.w = (xv.w - m) * r * gv.w + bv.w;
    __half2 h01 = __floats2half2_rn(o.x, o.y);
    __half2 h23 = __floats2half2_rn(o.z, o.w);
    uint2 hp = make_uint2(*(uint32_t*)&h01, *(uint32_t*)&h23);
    ((uint2*)g_xnh)[i4] = hp;   // GEMM operand AND residual (fp16)
}

// ---------------- fp16 mma.sync TN GEMM: D = A[M,K] @ B[N,K]^T ------------------
// 128x128 CTA tile, 8 warps of 64x32, kc=64 halves, 3-stage cp.async ring,
// ldmatrix fragment loads. 96 KB smem -> 2 CTAs/SM.
// QKVE: merged QKV projection epilogue (cols<512 -> qk, cols>=512 -> vT).
// RES: + fp16 residual (normalized input).
#define NSTAGE 3
#define STAGE_BYTES 16384            // 128x64 halves
#define SM_B (NSTAGE*STAGE_BYTES)
#define GSMEM (2*NSTAGE*STAGE_BYTES) // 96 KB

template<bool BIAS, bool RES, bool EXP, bool NORM, bool OUTF32, bool QKVE>
__global__ __launch_bounds__(256, 2) void gemm_h(
    const __half* __restrict__ A, const __half* __restrict__ B,
    const float* __restrict__ bias, const __half* __restrict__ res,
    __half* __restrict__ vtp,
    void* __restrict__ Cv, int lda, int ldb, int ldc, int K,
    long sA, long sB, long sC, float scale)
{
    extern __shared__ char smem[];
    const uint32_t sb = smem_u32(smem);
    const int tid = threadIdx.x, wid = tid >> 5, lane = tid & 31;
    const int gid = lane >> 2, tig = lane & 3;
    const int row0 = blockIdx.y * 128, col0 = blockIdx.x * 128;
    const int wm = (wid & 1) * 64, wn = (wid >> 1) * 32;
    const __half* Ab = A + (size_t)blockIdx.z * sA;
    const __half* Bb = B + (size_t)blockIdx.z * sB;

    float acc[4][4][4];
#pragma unroll
    for (int i = 0; i < 4; i++)
#pragma unroll
        for (int j = 0; j < 4; j++)
#pragma unroll
            for (int e = 0; e < 4; e++) acc[i][j][e] = 0.f;

    float rowpart[4][2];
    if (NORM) {
#pragma unroll
        for (int i = 0; i < 4; i++) { rowpart[i][0] = 0.f; rowpart[i][1] = 0.f; }
    }

    const int nk = K >> 6;   // 64 halves per chunk

    const int amr = wm + (lane & 15);
    const int ahv = lane >> 4;
    const int ar7 = amr & 7;
    const int bnr = wn + (lane & 7) + ((lane >> 4) << 3);
    const int bhv = (lane >> 3) & 1;
    const int br7 = bnr & 7;

    auto load_chunk = [&](int ck, int st) {
        uint32_t ab = sb + st * STAGE_BYTES;
        uint32_t bbs = sb + SM_B + st * STAGE_BYTES;
        int k0 = ck * 64;
#pragma unroll
        for (int j = 0; j < 4; j++) {
            int s = tid + 256 * j;
            int r = s >> 3, g = s & 7;
            uint32_t off = (uint32_t)(r * 128 + ((g ^ (r & 7)) << 4));
            cp16(ab + off, Ab + (size_t)(row0 + r) * lda + k0 + g * 8);
            cp16(bbs + off, Bb + (size_t)(col0 + r) * ldb + k0 + g * 8);
        }
    };

#pragma unroll
    for (int p = 0; p < NSTAGE - 1; p++) {
        if (p < nk) load_chunk(p, p);
        asm volatile("cp.async.commit_group;" ::: "memory");
    }

    int st = 0, stl = NSTAGE - 1;
    for (int i = 0; i < nk; i++) {
        asm volatile("cp.async.wait_group %0;" :: "n"(NSTAGE - 2) : "memory");
        __syncthreads();
        if (i + NSTAGE - 1 < nk) load_chunk(i + NSTAGE - 1, stl);
        asm volatile("cp.async.commit_group;" ::: "memory");

        uint32_t as = sb + st * STAGE_BYTES + (uint32_t)(amr * 128);
        uint32_t bs = sb + SM_B + st * STAGE_BYTES + (uint32_t)(bnr * 128);
#pragma unroll
        for (int k16 = 0; k16 < 4; k16++) {
            uint32_t af[4][4], bf[4][2];
            uint32_t aswz = (uint32_t)(((k16 * 2 + ahv) ^ ar7) << 4);
            uint32_t bswz = (uint32_t)(((k16 * 2 + bhv) ^ br7) << 4);
#pragma unroll
            for (int mi = 0; mi < 4; mi++)
                ldsm4(af[mi][0], af[mi][1], af[mi][2], af[mi][3],
                      as + aswz + mi * 2048);
            ldsm4(bf[0][0], bf[0][1], bf[1][0], bf[1][1], bs + bswz);
            ldsm4(bf[2][0], bf[2][1], bf[3][0], bf[3][1], bs + bswz + 2048);
#pragma unroll
            for (int mi = 0; mi < 4; mi++)
#pragma unroll
                for (int ni = 0; ni < 4; ni++)
                    mma16816(acc[mi][ni], af[mi], bf[ni]);
            if (NORM) {
#pragma unroll
                for (int mi = 0; mi < 4; mi++) {
                    rowpart[mi][0] += h2sum(af[mi][0]) + h2sum(af[mi][2]);
                    rowpart[mi][1] += h2sum(af[mi][1]) + h2sum(af[mi][3]);
                }
            }
        }
        st = (st + 1 == NSTAGE) ? 0 : st + 1;
        stl = (stl + 1 == NSTAGE) ? 0 : stl + 1;
    }

    if (NORM) {
#pragma unroll
        for (int mi = 0; mi < 4; mi++)
#pragma unroll
            for (int h = 0; h < 2; h++) {
                float s = rowpart[mi][h];
                s += __shfl_xor_sync(0xffffffffu, s, 1);
                s += __shfl_xor_sync(0xffffffffu, s, 2);
                rowpart[mi][h] = 1.f / s;
            }
    }

    // epilogue: c0,c1 at (row gid, col tig*2,+1); c2,c3 at row+8
#pragma unroll
    for (int mi = 0; mi < 4; mi++) {
#pragma unroll
        for (int ni = 0; ni < 4; ni++) {
            int r0 = row0 + wm + mi * 16 + gid;
            int c = col0 + wn + ni * 8 + tig * 2;
#pragma unroll
            for (int h = 0; h < 2; h++) {
                int r = r0 + h * 8;
                float v0 = acc[mi][ni][h * 2 + 0] * scale;
                float v1 = acc[mi][ni][h * 2 + 1] * scale;
                if (NORM) {
                    float inv = rowpart[mi][h];
                    v0 *= inv; v1 *= inv;
                }
                if (EXP) { v0 = __expf(v0); v1 = __expf(v1); }
                if (BIAS) {
                    float2 bb = *(const float2*)(bias + c);
                    v0 += bb.x; v1 += bb.y;
                }
                if (RES) {
                    __half2 rh = *(const __half2*)(res + (size_t)r * ldc + c);
                    float2 rr = __half22float2(rh);
                    v0 += rr.x; v1 += rr.y;
                }
                if (QKVE) {
                    // cols 0-511: q|k row-major (ldc=512); cols 512-767: vT
                    if (c < 512) {
                        __half* Cb = (__half*)Cv;
                        __half2 hv = __floats2half2_rn(v0, v1);
                        *(__half2*)(Cb + (size_t)r * 512 + c) = hv;
                    } else {
                        vtp[(size_t)(c - 512) * ROWS_TOT + r] = __float2half(v0);
                        vtp[(size_t)(c - 511) * ROWS_TOT + r] = __float2half(v1);
                    }
                } else if (OUTF32) {
                    float* Cb = (float*)Cv + (size_t)blockIdx.z * sC;
                    *(float2*)(Cb + (size_t)r * ldc + c) = make_float2(v0, v1);
                } else {
                    __half* Cb = (__half*)Cv + (size_t)blockIdx.z * sC;
                    __half2 hv = __floats2half2_rn(v0, v1);
                    *(__half2*)(Cb + (size_t)r * ldc + c) = hv;
                }
            }
        }
    }
}

// -------------------------------- launch ---------------------------------------
extern "C" void kernel_launch(void* const* d_in, const int* in_sizes, int n_in,
                              void* d_out, int out_size) {
    const float* x     = (const float*)d_in[0];
    const float* gamma = (const float*)d_in[1];
    const float* beta  = (const float*)d_in[2];
    const float* Wq    = (const float*)d_in[3];
    const float* bq    = (const float*)d_in[4];
    const float* Wk    = (const float*)d_in[5];
    const float* bk    = (const float*)d_in[6];
    const float* Wv    = (const float*)d_in[7];
    const float* bv    = (const float*)d_in[8];
    const float* Wp    = (const float*)d_in[9];
    const float* bp    = (const float*)d_in[10];
    float* out = (float*)d_out;
    (void)in_sizes; (void)n_in; (void)out_size;

    float* b3;
    __half *xnh, *qk, *vT, *o, *attn, *wt;
    cudaGetSymbolAddress((void**)&b3,   g_b3);
    cudaGetSymbolAddress((void**)&xnh,  g_xnh);
    cudaGetSymbolAddress((void**)&qk,   g_qk);
    cudaGetSymbolAddress((void**)&vT,   g_vT);
    cudaGetSymbolAddress((void**)&o,    g_o);
    cudaGetSymbolAddress((void**)&attn, g_attn);
    cudaGetSymbolAddress((void**)&wt,   g_wt);
    __half* wtqkv = wt;               // wtq|wtk|wtv: 768 rows of 256
    __half* wtp   = wt + 3*C_*C_;

    cudaFuncSetAttribute(gemm_h<true,false,false,false,false,true>,  cudaFuncAttributeMaxDynamicSharedMemorySize, GSMEM);
    cudaFuncSetAttribute(gemm_h<false,false,true,false,false,false>, cudaFuncAttributeMaxDynamicSharedMemorySize, GSMEM);
    cudaFuncSetAttribute(gemm_h<false,false,false,true,false,false>, cudaFuncAttributeMaxDynamicSharedMemorySize, GSMEM);
    cudaFuncSetAttribute(gemm_h<true,true,false,false,true,false>,   cudaFuncAttributeMaxDynamicSharedMemorySize, GSMEM);

    // launch idx: 0 prep, 1 gn_norm, 2 qkvProj, 3 QKT, 4 PV, 5 outProj
    dim3 gp(32, 10);
    prep<<<gp, 256>>>(x, Wq, Wk, Wv, Wp, bq, bk, bv);
    gn_norm<<<(ROWS_TOT * C_ / 4) / 256, 256>>>(x, gamma, beta);

    // merged QKV projection: [16384,256] @ [256,768] + b3 -> qk (cols<512), vT
    dim3 gQKV(6, 128, 1);
    gemm_h<true,false,false,false,false,true><<<gQKV, 256, GSMEM>>>(
        xnh, wtqkv, b3, nullptr, vT, qk, C_, C_, 512, C_, 0, 0, 0, 1.f);

    // E = exp((Q @ K^T) / 16), batched, unnormalized, fp16
    dim3 gS(32, 32, B_);
    gemm_h<false,false,true,false,false,false><<<gS, 256, GSMEM>>>(
        qk, qk + 256, nullptr, nullptr, nullptr, attn, 512, 512, NTOK, C_,
        (long)NTOK * 512, (long)NTOK * 512, (long)NTOK * NTOK, 0.0625f);

    // O = (E @ V) / rowsum(E)  (row sums from fp16 E fragments) -> fp16
    dim3 gAV(2, 32, B_);
    gemm_h<false,false,false,true,false,false><<<gAV, 256, GSMEM>>>(
        attn, vT, nullptr, nullptr, nullptr, o, NTOK, ROWS_TOT, C_, NTOK,
        (long)NTOK * NTOK, (long)NTOK, (long)NTOK * C_, 1.f);

    // final projection + bias + fp16 residual -> d_out (fp32)
    dim3 gP(2, 128, 1);
    gemm_h<true,true,false,false,true,false><<<gP, 256, GSMEM>>>(
        o, wtp, bp, xnh, nullptr, out, C_, C_, C_, C_, 0, 0, 0, 1.f);
}